// round 7
// baseline (speedup 1.0000x reference)
#include <cuda_runtime.h>
#include <cuda_bf16.h>
#include <cuda_fp8.h>
#include <math.h>
#include <stdint.h>

#define S_LEN 2048
#define D_MODEL 2048
#define N_HEADS 16
#define HD 128
#define E3 (3 * D_MODEL)   // 6144

// scales: hi fp8 stored = 32*x ; lo fp8 stored = 32*512*(x - bf16(x))
// value(cross product) = stored_product * 2^-19
#define F8SCALE_HI 32.0f
#define F8SCALE_LO 16384.0f
#define F8FACTOR (1.0f / 524288.0f)   // 2^-19

// ---------------- scratch (static device globals; no allocations) -------------
__device__ float g_qkv[(size_t)S_LEN * E3];                      // fp32 qkv
__device__ float g_scores[(size_t)N_HEADS * S_LEN * S_LEN];      // fp32 logits

__device__ __nv_bfloat16 g_xh[(size_t)S_LEN * D_MODEL];
__device__ uint8_t       g_x8[(size_t)S_LEN * D_MODEL],  g_xl8[(size_t)S_LEN * D_MODEL];
__device__ __nv_bfloat16 g_wqh[(size_t)E3 * D_MODEL];
__device__ uint8_t       g_wq8[(size_t)E3 * D_MODEL],    g_wql8[(size_t)E3 * D_MODEL];
__device__ __nv_bfloat16 g_woh[(size_t)D_MODEL * D_MODEL];
__device__ uint8_t       g_wo8[(size_t)D_MODEL * D_MODEL], g_wol8[(size_t)D_MODEL * D_MODEL];
__device__ __nv_bfloat16 g_qhh[(size_t)S_LEN * D_MODEL];
__device__ uint8_t       g_q8[(size_t)S_LEN * D_MODEL],  g_ql8[(size_t)S_LEN * D_MODEL];
__device__ __nv_bfloat16 g_khh[(size_t)S_LEN * D_MODEL];
__device__ uint8_t       g_k8[(size_t)S_LEN * D_MODEL],  g_kl8[(size_t)S_LEN * D_MODEL];
__device__ __nv_bfloat16 g_vth[(size_t)D_MODEL * S_LEN];
__device__ uint8_t       g_vt8[(size_t)D_MODEL * S_LEN], g_vtl8[(size_t)D_MODEL * S_LEN];
__device__ __nv_bfloat16 g_ath[(size_t)S_LEN * D_MODEL];
__device__ uint8_t       g_at8[(size_t)S_LEN * D_MODEL], g_atl8[(size_t)S_LEN * D_MODEL];
__device__ __nv_bfloat16 g_ph[(size_t)N_HEADS * S_LEN * S_LEN];
__device__ uint8_t       g_p8[(size_t)N_HEADS * S_LEN * S_LEN];
__device__ uint8_t       g_pl8[(size_t)N_HEADS * S_LEN * S_LEN];

// =============================================================================
// helpers (base-ISA only)
// =============================================================================
__device__ __forceinline__ uint32_t smem_u32(const void* p) {
    uint32_t a;
    asm("{ .reg .u64 t; cvta.to.shared.u64 t, %1; cvt.u32.u64 %0, t; }" : "=r"(a) : "l"(p));
    return a;
}
__device__ __forceinline__ void cp16(uint32_t dst, const void* src) {
    asm volatile("cp.async.cg.shared.global [%0], [%1], 16;" :: "r"(dst), "l"(src));
}
#define CP_COMMIT() asm volatile("cp.async.commit_group;" ::: "memory")
#define CP_WAIT(n)  asm volatile("cp.async.wait_group %0;" :: "n"(n) : "memory")

__device__ __forceinline__ void ldm4(uint32_t* r, uint32_t addr) {
    asm volatile("ldmatrix.sync.aligned.m8n8.x4.shared.b16 {%0,%1,%2,%3}, [%4];"
                 : "=r"(r[0]), "=r"(r[1]), "=r"(r[2]), "=r"(r[3]) : "r"(addr));
}
__device__ __forceinline__ void mma16816(float* d, const uint32_t* a, uint32_t b0, uint32_t b1) {
    asm volatile(
        "mma.sync.aligned.m16n8k16.row.col.f32.bf16.bf16.f32 "
        "{%0,%1,%2,%3}, {%4,%5,%6,%7}, {%8,%9}, {%0,%1,%2,%3};"
        : "+f"(d[0]), "+f"(d[1]), "+f"(d[2]), "+f"(d[3])
        : "r"(a[0]), "r"(a[1]), "r"(a[2]), "r"(a[3]), "r"(b0), "r"(b1));
}
__device__ __forceinline__ void mma16832f8(float* d, const uint32_t* a, uint32_t b0, uint32_t b1) {
    asm volatile(
        "mma.sync.aligned.m16n8k32.row.col.f32.e4m3.e4m3.f32 "
        "{%0,%1,%2,%3}, {%4,%5,%6,%7}, {%8,%9}, {%0,%1,%2,%3};"
        : "+f"(d[0]), "+f"(d[1]), "+f"(d[2]), "+f"(d[3])
        : "r"(a[0]), "r"(a[1]), "r"(a[2]), "r"(a[3]), "r"(b0), "r"(b1));
}

__device__ __forceinline__ uint8_t f2e4m3(float x) {
    return (uint8_t)__nv_cvt_float_to_fp8(x, __NV_SATFINITE, __NV_E4M3);
}
// produce hi bf16 + hi fp8 + lo fp8 for one value
__device__ __forceinline__ void split3(float x, __nv_bfloat16& h, uint8_t& v8, uint8_t& l8) {
    h = __float2bfloat16(x);
    const float l = x - __bfloat162float(h);
    v8 = f2e4m3(F8SCALE_HI * x);
    l8 = f2e4m3(F8SCALE_LO * l);
}

// =============================================================================
// hybrid bf16+fp8 NT GEMM on mma.sync: C[m,n] = scale * sum_k A[m,k]*B[n,k]
// hi pass: bf16 m16n8k16 (Ah*Bh). cross passes: e4m3 m16n8k32
// (A8*Bl8 + Al8*B8), both scaled by 2^-19, single fp32 accumulator.
// CTA 128x128, K-tile 64, 3-stage cp.async pipeline, 256 threads,
// 8 warps as 2(m) x 4(n): warp tile 64x32.
// =============================================================================
#define OFF_AH   0          // 128 x 128B (bf16, 8-col xor swizzle)
#define OFF_BH   16384
#define OFF_A8   32768      // 128 x  64B (fp8, 4-col xor swizzle)
#define OFF_AL8  40960
#define OFF_B8   49152
#define OFF_BL8  57344
#define STAGE_B  65536
#define NSTAGE   3
#define GEMM_SMEM (NSTAGE * STAGE_B)   // 192 KB

__global__ void __launch_bounds__(256, 1) gemm_tc_kernel(
    const __nv_bfloat16* __restrict__ Ah, const uint8_t* __restrict__ A8,
    const uint8_t* __restrict__ Al8,
    const __nv_bfloat16* __restrict__ Bh, const uint8_t* __restrict__ B8,
    const uint8_t* __restrict__ Bl8,
    float* __restrict__ C,
    __nv_bfloat16* __restrict__ Ch, uint8_t* __restrict__ C8, uint8_t* __restrict__ Cl8,
    int K, int lda, int ldb, int ldc,
    long long aZ, long long bZ, long long cZ, float scale)
{
    extern __shared__ __align__(128) char smem[];
    const uint32_t sb = smem_u32(smem);
    const int tid = threadIdx.x;
    const int lane = tid & 31;
    const int wid = tid >> 5;
    const int wm = wid & 1;           // m offset 64*wm
    const int wn = wid >> 1;          // n offset 32*wn (0..3)

    Ah += blockIdx.z * aZ;  A8 += blockIdx.z * aZ;  Al8 += blockIdx.z * aZ;
    Bh += blockIdx.z * bZ;  B8 += blockIdx.z * bZ;  Bl8 += blockIdx.z * bZ;
    const int m0 = blockIdx.y * 128;
    const int n0 = blockIdx.x * 128;

    float acch[4][4][4];              // Ah*Bh (bf16)
    float accl[4][4][4];              // fp8 cross terms (stored units)
#pragma unroll
    for (int a = 0; a < 4; a++)
#pragma unroll
        for (int b = 0; b < 4; b++)
#pragma unroll
            for (int c = 0; c < 4; c++) { acch[a][b][c] = 0.0f; accl[a][b][c] = 0.0f; }

    const int nt = K / 64;

    auto load_stage = [&](int t, int buf) {
        const uint32_t base = sb + (uint32_t)buf * STAGE_B;
        // bf16 hi tiles: 1024 chunks each
#pragma unroll
        for (int i = 0; i < 4; i++) {
            const int cid = tid + 256 * i;     // 0..1023
            const int row = cid >> 3;          // 0..127
            const int c   = cid & 7;
            const uint32_t phys = (uint32_t)(row * 128 + ((c ^ (row & 7)) << 4));
            const size_t ga = (size_t)(m0 + row) * lda + (size_t)t * 64 + c * 8;
            const size_t gb = (size_t)(n0 + row) * ldb + (size_t)t * 64 + c * 8;
            cp16(base + OFF_AH + phys, Ah + ga);
            cp16(base + OFF_BH + phys, Bh + gb);
        }
        // fp8 tiles: 512 chunks each (64B rows)
#pragma unroll
        for (int i = 0; i < 2; i++) {
            const int cid = tid + 256 * i;     // 0..511
            const int row = cid >> 2;          // 0..127
            const int c   = cid & 3;
            const uint32_t phys = (uint32_t)(row * 64 + ((c ^ (row & 3)) << 4));
            const size_t ga = (size_t)(m0 + row) * lda + (size_t)t * 64 + c * 16;
            const size_t gb = (size_t)(n0 + row) * ldb + (size_t)t * 64 + c * 16;
            cp16(base + OFF_A8  + phys, A8  + ga);
            cp16(base + OFF_AL8 + phys, Al8 + ga);
            cp16(base + OFF_B8  + phys, B8  + gb);
            cp16(base + OFF_BL8 + phys, Bl8 + gb);
        }
        CP_COMMIT();
    };

    load_stage(0, 0);
    if (nt > 1) load_stage(1, 1);

    const int ar = wm * 64 + (lane & 15);
    const int br = wn * 32 + (lane & 15);

    int buf = 0;
    for (int t = 0; t < nt; t++) {
        if (t + 1 < nt) { CP_WAIT(1); } else { CP_WAIT(0); }
        __syncthreads();

        if (t + 2 < nt) {
            int nb = buf + 2; if (nb >= NSTAGE) nb -= NSTAGE;
            load_stage(t + 2, nb);
        }

        const uint32_t tb = sb + (uint32_t)buf * STAGE_B;

        // ---- bf16 hi pass: 4 x k16 ----
#pragma unroll
        for (int k16 = 0; k16 < 4; k16++) {
            const int cb = k16 * 2 + (lane >> 4);
            uint32_t ahf[4][4];
#pragma unroll
            for (int mb = 0; mb < 4; mb++) {
                const int R = ar + mb * 16;
                ldm4(ahf[mb], tb + OFF_AH + (uint32_t)(R * 128 + ((cb ^ (R & 7)) << 4)));
            }
            uint32_t bhf[2][4];
#pragma unroll
            for (int q = 0; q < 2; q++) {
                const int R = br + q * 16;
                ldm4(bhf[q], tb + OFF_BH + (uint32_t)(R * 128 + ((cb ^ (R & 7)) << 4)));
            }
#pragma unroll
            for (int mb = 0; mb < 4; mb++)
#pragma unroll
                for (int q = 0; q < 2; q++) {
                    mma16816(acch[mb][2 * q],     ahf[mb], bhf[q][0], bhf[q][2]);
                    mma16816(acch[mb][2 * q + 1], ahf[mb], bhf[q][1], bhf[q][3]);
                }
        }

        // ---- fp8 cross passes: 2 x k32 ----
#pragma unroll
        for (int kk = 0; kk < 2; kk++) {
            const int cb = kk * 2 + (lane >> 4);   // 16B chunk 0..3 of 64B row
            uint32_t a8f[4][4], al8f[4][4];
#pragma unroll
            for (int mb = 0; mb < 4; mb++) {
                const int R = ar + mb * 16;
                const uint32_t phys = (uint32_t)(R * 64 + ((cb ^ (R & 3)) << 4));
                ldm4(a8f[mb],  tb + OFF_A8  + phys);
                ldm4(al8f[mb], tb + OFF_AL8 + phys);
            }
            uint32_t b8f[2][4], bl8f[2][4];
#pragma unroll
            for (int q = 0; q < 2; q++) {
                const int R = br + q * 16;
                const uint32_t phys = (uint32_t)(R * 64 + ((cb ^ (R & 3)) << 4));
                ldm4(b8f[q],  tb + OFF_B8  + phys);
                ldm4(bl8f[q], tb + OFF_BL8 + phys);
            }
#pragma unroll
            for (int mb = 0; mb < 4; mb++)
#pragma unroll
                for (int q = 0; q < 2; q++) {
                    mma16832f8(accl[mb][2 * q],     a8f[mb],  bl8f[q][0], bl8f[q][2]);
                    mma16832f8(accl[mb][2 * q],     al8f[mb], b8f[q][0],  b8f[q][2]);
                    mma16832f8(accl[mb][2 * q + 1], a8f[mb],  bl8f[q][1], bl8f[q][3]);
                    mma16832f8(accl[mb][2 * q + 1], al8f[mb], b8f[q][1],  b8f[q][3]);
                }
        }
        if (++buf == NSTAGE) buf = 0;
    }

    // ---- epilogue ----
    const int g  = lane >> 2;
    const int tg = lane & 3;
    if (C) {
        C += blockIdx.z * cZ;
#pragma unroll
        for (int mb = 0; mb < 4; mb++) {
            const int row = m0 + wm * 64 + mb * 16 + g;
#pragma unroll
            for (int nb = 0; nb < 4; nb++) {
                const int col = n0 + wn * 32 + nb * 8 + tg * 2;
                float2 v0, v1;
                v0.x = (acch[mb][nb][0] + F8FACTOR * accl[mb][nb][0]) * scale;
                v0.y = (acch[mb][nb][1] + F8FACTOR * accl[mb][nb][1]) * scale;
                v1.x = (acch[mb][nb][2] + F8FACTOR * accl[mb][nb][2]) * scale;
                v1.y = (acch[mb][nb][3] + F8FACTOR * accl[mb][nb][3]) * scale;
                *(float2*)(C + (size_t)row * ldc + col)       = v0;
                *(float2*)(C + (size_t)(row + 8) * ldc + col) = v1;
            }
        }
    } else {
        Ch  += blockIdx.z * cZ;
        C8  += blockIdx.z * cZ;
        Cl8 += blockIdx.z * cZ;
#pragma unroll
        for (int mb = 0; mb < 4; mb++) {
            const int row = m0 + wm * 64 + mb * 16 + g;
#pragma unroll
            for (int nb = 0; nb < 4; nb++) {
                const int col = n0 + wn * 32 + nb * 8 + tg * 2;
#pragma unroll
                for (int half = 0; half < 2; half++) {
                    const size_t o = (size_t)(row + 8 * half) * ldc + col;
                    const float va = (acch[mb][nb][2 * half]     + F8FACTOR * accl[mb][nb][2 * half])     * scale;
                    const float vb = (acch[mb][nb][2 * half + 1] + F8FACTOR * accl[mb][nb][2 * half + 1]) * scale;
                    __align__(4) __nv_bfloat16 hb[2];
                    uint8_t a8v[2], l8v[2];
                    split3(va, hb[0], a8v[0], l8v[0]);
                    split3(vb, hb[1], a8v[1], l8v[1]);
                    *(uint32_t*)(Ch + o) = *(uint32_t*)hb;
                    *(uint16_t*)(C8 + o) = *(uint16_t*)a8v;
                    *(uint16_t*)(Cl8 + o) = *(uint16_t*)l8v;
                }
            }
        }
    }
}

// =============================================================================
// split3 kernel: fp32 -> bf16 hi + fp8 hi + fp8 lo
// =============================================================================
__global__ void __launch_bounds__(256) split3_kernel(
    const float* __restrict__ src, __nv_bfloat16* __restrict__ dh,
    uint8_t* __restrict__ d8, uint8_t* __restrict__ dl8, long long n4)
{
    const long long i = (long long)blockIdx.x * 256 + threadIdx.x;
    if (i >= n4) return;
    float4 v = ((const float4*)src)[i];
    __align__(8) __nv_bfloat16 hb[4];
    __align__(4) uint8_t a8[4], l8[4];
    split3(v.x, hb[0], a8[0], l8[0]);
    split3(v.y, hb[1], a8[1], l8[1]);
    split3(v.z, hb[2], a8[2], l8[2]);
    split3(v.w, hb[3], a8[3], l8[3]);
    ((uint2*)dh)[i] = *(uint2*)hb;
    ((uint32_t*)d8)[i] = *(uint32_t*)a8;
    ((uint32_t*)dl8)[i] = *(uint32_t*)l8;
}

// =============================================================================
// RoPE + split3
// =============================================================================
__global__ void __launch_bounds__(1024) rope_split_kernel(
    const float* __restrict__ qkv,
    __nv_bfloat16* __restrict__ qh, uint8_t* __restrict__ q8, uint8_t* __restrict__ ql8,
    __nv_bfloat16* __restrict__ kh, uint8_t* __restrict__ k8, uint8_t* __restrict__ kl8)
{
    __shared__ float s_inv[64];
    const int s = blockIdx.x;
    const int t = threadIdx.x;
    if (t < 64) s_inv[t] = (float)pow(10000.0, -(double)(2 * t) / 128.0);
    __syncthreads();

    const int h = t >> 6;
    const int j = t & 63;
    const float ang = (float)((double)s * (double)s_inv[j]);
    float sn, cs;
    sincosf(ang, &sn, &cs);

    const float* q = qkv + (size_t)s * E3 + h * HD;
    const float* k = q + D_MODEL;
    const size_t ob = (size_t)s * D_MODEL + h * HD;

    const float q1 = q[j], q2 = q[j + 64];
    const float k1 = k[j], k2 = k[j + 64];
    __nv_bfloat16 hh; uint8_t v8, l8;
    split3(q1 * cs - q2 * sn, hh, v8, l8); qh[ob + j] = hh;      q8[ob + j] = v8;      ql8[ob + j] = l8;
    split3(q2 * cs + q1 * sn, hh, v8, l8); qh[ob + j + 64] = hh; q8[ob + j + 64] = v8; ql8[ob + j + 64] = l8;
    split3(k1 * cs - k2 * sn, hh, v8, l8); kh[ob + j] = hh;      k8[ob + j] = v8;      kl8[ob + j] = l8;
    split3(k2 * cs + k1 * sn, hh, v8, l8); kh[ob + j + 64] = hh; k8[ob + j + 64] = v8; kl8[ob + j + 64] = l8;
}

// =============================================================================
// V transpose + split3
// =============================================================================
__global__ void __launch_bounds__(256) vtrans_split_kernel(
    const float* __restrict__ qkv,
    __nv_bfloat16* __restrict__ vth, uint8_t* __restrict__ vt8, uint8_t* __restrict__ vtl8)
{
    __shared__ float tile[32][33];
    const int c0 = blockIdx.x * 32;
    const int s0 = blockIdx.y * 32;
    const int tx = threadIdx.x & 31;
    const int ty = threadIdx.x >> 5;

#pragma unroll
    for (int r = ty; r < 32; r += 8)
        tile[r][tx] = qkv[(size_t)(s0 + r) * E3 + 2 * D_MODEL + c0 + tx];
    __syncthreads();
#pragma unroll
    for (int r = ty; r < 32; r += 8) {
        const float v = tile[tx][r];
        __nv_bfloat16 hh; uint8_t v8, l8;
        split3(v, hh, v8, l8);
        const size_t o = (size_t)(c0 + r) * S_LEN + s0 + tx;
        vth[o] = hh;
        vt8[o] = v8;
        vtl8[o] = l8;
    }
}

// =============================================================================
// softmax: fp32 scores row -> bf16 hi + fp8 hi + fp8 lo probabilities
// =============================================================================
__global__ void __launch_bounds__(256) softmax_kernel(
    const float* __restrict__ scores,
    __nv_bfloat16* __restrict__ ph, uint8_t* __restrict__ p8, uint8_t* __restrict__ pl8)
{
    const long long row = blockIdx.x;
    const float* p = scores + row * S_LEN;
    const int t = threadIdx.x;
    const int lane = t & 31, warp = t >> 5;

    __shared__ float red[8];

    float4 u0 = ((const float4*)p)[t * 2];
    float4 u1 = ((const float4*)p)[t * 2 + 1];
    float v[8] = {u0.x, u0.y, u0.z, u0.w, u1.x, u1.y, u1.z, u1.w};

    float mx = -INFINITY;
#pragma unroll
    for (int i = 0; i < 8; i++) mx = fmaxf(mx, v[i]);
#pragma unroll
    for (int o = 16; o; o >>= 1) mx = fmaxf(mx, __shfl_xor_sync(0xffffffffu, mx, o));
    if (lane == 0) red[warp] = mx;
    __syncthreads();
    if (t < 32) {
        float x = (t < 8) ? red[t] : -INFINITY;
#pragma unroll
        for (int o = 4; o; o >>= 1) x = fmaxf(x, __shfl_xor_sync(0xffffffffu, x, o));
        if (t == 0) red[0] = x;
    }
    __syncthreads();
    mx = red[0];
    __syncthreads();

    float sum = 0.0f;
#pragma unroll
    for (int i = 0; i < 8; i++) {
        v[i] = __expf(v[i] - mx);
        sum += v[i];
    }
#pragma unroll
    for (int o = 16; o; o >>= 1) sum += __shfl_xor_sync(0xffffffffu, sum, o);
    if (lane == 0) red[warp] = sum;
    __syncthreads();
    if (t < 32) {
        float x = (t < 8) ? red[t] : 0.0f;
#pragma unroll
        for (int o = 4; o; o >>= 1) x += __shfl_xor_sync(0xffffffffu, x, o);
        if (t == 0) red[0] = x;
    }
    __syncthreads();
    const float r = 1.0f / red[0];

    __align__(16) __nv_bfloat16 hb[8];
    __align__(8) uint8_t a8[8], l8[8];
#pragma unroll
    for (int i = 0; i < 8; i++) split3(v[i] * r, hb[i], a8[i], l8[i]);
    const size_t ob = (size_t)row * S_LEN + (size_t)t * 8;
    *(uint4*)(ph + ob) = *(uint4*)hb;
    *(uint2*)(p8 + ob) = *(uint2*)a8;
    *(uint2*)(pl8 + ob) = *(uint2*)l8;
}

// =============================================================================
// launch
// =============================================================================
extern "C" void kernel_launch(void* const* d_in, const int* in_sizes, int n_in,
                              void* d_out, int out_size)
{
    (void)in_sizes; (void)n_in; (void)out_size;
    const float* x     = (const float*)d_in[0];   // [1, 2048, 2048]
    const float* w_qkv = (const float*)d_in[1];   // [6144, 2048]
    const float* w_out = (const float*)d_in[2];   // [2048, 2048]
    float* out = (float*)d_out;                   // [1, 2048, 2048]

    float *qkv, *scores;
    cudaGetSymbolAddress((void**)&qkv,    g_qkv);
    cudaGetSymbolAddress((void**)&scores, g_scores);
    __nv_bfloat16 *xh, *wqh, *woh, *qh, *kh, *vth, *ath, *ph;
    uint8_t *x8, *xl8, *wq8, *wql8, *wo8, *wol8, *q8, *ql8, *k8, *kl8;
    uint8_t *vt8, *vtl8, *at8, *atl8, *p8, *pl8;
    cudaGetSymbolAddress((void**)&xh,   g_xh);
    cudaGetSymbolAddress((void**)&x8,   g_x8);   cudaGetSymbolAddress((void**)&xl8,  g_xl8);
    cudaGetSymbolAddress((void**)&wqh,  g_wqh);
    cudaGetSymbolAddress((void**)&wq8,  g_wq8);  cudaGetSymbolAddress((void**)&wql8, g_wql8);
    cudaGetSymbolAddress((void**)&woh,  g_woh);
    cudaGetSymbolAddress((void**)&wo8,  g_wo8);  cudaGetSymbolAddress((void**)&wol8, g_wol8);
    cudaGetSymbolAddress((void**)&qh,   g_qhh);
    cudaGetSymbolAddress((void**)&q8,   g_q8);   cudaGetSymbolAddress((void**)&ql8,  g_ql8);
    cudaGetSymbolAddress((void**)&kh,   g_khh);
    cudaGetSymbolAddress((void**)&k8,   g_k8);   cudaGetSymbolAddress((void**)&kl8,  g_kl8);
    cudaGetSymbolAddress((void**)&vth,  g_vth);
    cudaGetSymbolAddress((void**)&vt8,  g_vt8);  cudaGetSymbolAddress((void**)&vtl8, g_vtl8);
    cudaGetSymbolAddress((void**)&ath,  g_ath);
    cudaGetSymbolAddress((void**)&at8,  g_at8);  cudaGetSymbolAddress((void**)&atl8, g_atl8);
    cudaGetSymbolAddress((void**)&ph,   g_ph);
    cudaGetSymbolAddress((void**)&p8,   g_p8);   cudaGetSymbolAddress((void**)&pl8,  g_pl8);

    cudaFuncSetAttribute(gemm_tc_kernel, cudaFuncAttributeMaxDynamicSharedMemorySize, GEMM_SMEM);

    const float scale = 0.08838834764831845f;  // 1/sqrt(128)

    // 0) split inputs
    {
        long long n4;
        n4 = (long long)S_LEN * D_MODEL / 4;
        split3_kernel<<<(unsigned)((n4 + 255) / 256), 256>>>(x, xh, x8, xl8, n4);
        n4 = (long long)E3 * D_MODEL / 4;
        split3_kernel<<<(unsigned)((n4 + 255) / 256), 256>>>(w_qkv, wqh, wq8, wql8, n4);
        n4 = (long long)D_MODEL * D_MODEL / 4;
        split3_kernel<<<(unsigned)((n4 + 255) / 256), 256>>>(w_out, woh, wo8, wol8, n4);
    }

    // 1) QKV projection (fp32 out)
    {
        dim3 grid(E3 / 128, S_LEN / 128, 1);
        gemm_tc_kernel<<<grid, 256, GEMM_SMEM>>>(xh, x8, xl8, wqh, wq8, wql8,
                                                 qkv, nullptr, nullptr, nullptr,
                                                 D_MODEL, D_MODEL, D_MODEL, E3,
                                                 0, 0, 0, 1.0f);
    }

    // 2) RoPE + split3 q,k ; transpose + split3 v
    rope_split_kernel<<<S_LEN, 1024>>>(qkv, qh, q8, ql8, kh, k8, kl8);
    {
        dim3 grid(D_MODEL / 32, S_LEN / 32, 1);
        vtrans_split_kernel<<<grid, 256>>>(qkv, vth, vt8, vtl8);
    }

    // 3) scores (fp32 out)
    {
        dim3 grid(S_LEN / 128, S_LEN / 128, N_HEADS);
        gemm_tc_kernel<<<grid, 256, GEMM_SMEM>>>(qh, q8, ql8, kh, k8, kl8,
                                                 scores, nullptr, nullptr, nullptr,
                                                 HD, D_MODEL, D_MODEL, S_LEN,
                                                 HD, HD, (long long)S_LEN * S_LEN, scale);
    }

    // 4) softmax -> split3 probabilities
    softmax_kernel<<<N_HEADS * S_LEN, 256>>>(scores, ph, p8, pl8);

    // 5) PV (split3 bf16/fp8 out, fused)
    {
        dim3 grid(1, S_LEN / 128, N_HEADS);
        gemm_tc_kernel<<<grid, 256, GEMM_SMEM>>>(ph, p8, pl8, vth, vt8, vtl8,
                                                 nullptr, ath, at8, atl8,
                                                 S_LEN, S_LEN, S_LEN, D_MODEL,
                                                 (long long)S_LEN * S_LEN,
                                                 (long long)HD * S_LEN,
                                                 (long long)HD, 1.0f);
    }

    // 6) out projection (fp32 out)
    {
        dim3 grid(D_MODEL / 128, S_LEN / 128, 1);
        gemm_tc_kernel<<<grid, 256, GEMM_SMEM>>>(ath, at8, atl8, woh, wo8, wol8,
                                                 out, nullptr, nullptr, nullptr,
                                                 D_MODEL, D_MODEL, D_MODEL, D_MODEL,
                                                 0, 0, 0, 1.0f);
    }
}

// round 8
// speedup vs baseline: 2.2680x; 2.2680x over previous
#include <cuda_runtime.h>
#include <cuda_fp16.h>
#include <math.h>
#include <stdint.h>

#define S_LEN 2048
#define D_MODEL 2048
#define N_HEADS 16
#define HD 128
#define E3 (3 * D_MODEL)   // 6144

// ---------------- scratch (static device globals; no allocations) -------------
__device__ float g_qkv[(size_t)S_LEN * E3];                      // fp32 qkv
__device__ float g_scores[(size_t)N_HEADS * S_LEN * S_LEN];      // fp32 logits

__device__ __half g_x16[(size_t)S_LEN * D_MODEL];
__device__ __half g_wq16[(size_t)E3 * D_MODEL];
__device__ __half g_wo16[(size_t)D_MODEL * D_MODEL];
__device__ __half g_q16[(size_t)S_LEN * D_MODEL];
__device__ __half g_k16[(size_t)S_LEN * D_MODEL];
__device__ __half g_vt16[(size_t)D_MODEL * S_LEN];
__device__ __half g_at16[(size_t)S_LEN * D_MODEL];
__device__ __half g_p16[(size_t)N_HEADS * S_LEN * S_LEN];

// =============================================================================
// helpers (base-ISA only: mma.sync / ldmatrix / cp.async)
// =============================================================================
__device__ __forceinline__ uint32_t smem_u32(const void* p) {
    uint32_t a;
    asm("{ .reg .u64 t; cvta.to.shared.u64 t, %1; cvt.u32.u64 %0, t; }" : "=r"(a) : "l"(p));
    return a;
}
__device__ __forceinline__ void cp16(uint32_t dst, const void* src) {
    asm volatile("cp.async.cg.shared.global [%0], [%1], 16;" :: "r"(dst), "l"(src));
}
#define CP_COMMIT() asm volatile("cp.async.commit_group;" ::: "memory")
#define CP_WAIT(n)  asm volatile("cp.async.wait_group %0;" :: "n"(n) : "memory")

__device__ __forceinline__ void ldm4(uint32_t* r, uint32_t addr) {
    asm volatile("ldmatrix.sync.aligned.m8n8.x4.shared.b16 {%0,%1,%2,%3}, [%4];"
                 : "=r"(r[0]), "=r"(r[1]), "=r"(r[2]), "=r"(r[3]) : "r"(addr));
}
__device__ __forceinline__ void mma16816h(float* d, const uint32_t* a, uint32_t b0, uint32_t b1) {
    asm volatile(
        "mma.sync.aligned.m16n8k16.row.col.f32.f16.f16.f32 "
        "{%0,%1,%2,%3}, {%4,%5,%6,%7}, {%8,%9}, {%0,%1,%2,%3};"
        : "+f"(d[0]), "+f"(d[1]), "+f"(d[2]), "+f"(d[3])
        : "r"(a[0]), "r"(a[1]), "r"(a[2]), "r"(a[3]), "r"(b0), "r"(b1));
}

// =============================================================================
// fp16 NT GEMM on HMMA: C[m,n] = scale * sum_k A[m,k]*B[n,k]  (fp32 accum)
// CTA tile 128x128, K-tile 64, 4-stage cp.async pipeline, 256 threads,
// 8 warps as 2(m) x 4(n): warp tile 64x32.
// Epilogue: fp32 C, or fp16 Ch.
// =============================================================================
#define TILE_B 16384                 // 128 rows * 64 fp16 * 2B = 128B rows
#define STAGE_B (2 * TILE_B)         // A, B
#define NSTAGE 4
#define GEMM_SMEM (NSTAGE * STAGE_B) // 128 KB

__global__ void __launch_bounds__(256, 1) gemm_tc_kernel(
    const __half* __restrict__ A, const __half* __restrict__ B,
    float* __restrict__ C, __half* __restrict__ Ch,
    int K, int lda, int ldb, int ldc,
    long long aZ, long long bZ, long long cZ, float scale)
{
    extern __shared__ __align__(128) char smem[];
    const uint32_t sb = smem_u32(smem);
    const int tid = threadIdx.x;
    const int lane = tid & 31;
    const int wid = tid >> 5;
    const int wm = wid & 1;           // m offset 64*wm
    const int wn = wid >> 1;          // n offset 32*wn (0..3)

    A += blockIdx.z * aZ;
    B += blockIdx.z * bZ;
    const int m0 = blockIdx.y * 128;
    const int n0 = blockIdx.x * 128;

    float acc[4][4][4];
#pragma unroll
    for (int a = 0; a < 4; a++)
#pragma unroll
        for (int b = 0; b < 4; b++)
#pragma unroll
            for (int c = 0; c < 4; c++) acc[a][b][c] = 0.0f;

    const int nt = K / 64;

    auto load_stage = [&](int t, int buf) {
        const uint32_t base = sb + (uint32_t)buf * STAGE_B;
#pragma unroll
        for (int i = 0; i < 4; i++) {
            const int cid = tid + 256 * i;     // 0..1023
            const int row = cid >> 3;          // 0..127
            const int c   = cid & 7;           // 16B chunk in 128B row
            const uint32_t phys = (uint32_t)(row * 128 + ((c ^ (row & 7)) << 4));
            const size_t ga = (size_t)(m0 + row) * lda + (size_t)t * 64 + c * 8;
            const size_t gb = (size_t)(n0 + row) * ldb + (size_t)t * 64 + c * 8;
            cp16(base + 0 * TILE_B + phys, A + ga);
            cp16(base + 1 * TILE_B + phys, B + gb);
        }
        CP_COMMIT();
    };

    load_stage(0, 0);
    if (nt > 1) load_stage(1, 1);
    if (nt > 2) load_stage(2, 2);

    const int ar = wm * 64 + (lane & 15);
    const int br = wn * 32 + (lane & 15);

    int buf = 0;
    for (int t = 0; t < nt; t++) {
        if (t + 1 < nt) {
            if (t + 2 < nt) { CP_WAIT(2); } else { CP_WAIT(1); }
        } else {
            CP_WAIT(0);
        }
        __syncthreads();

        if (t + 3 < nt) {
            int nb = buf + 3; if (nb >= NSTAGE) nb -= NSTAGE;
            load_stage(t + 3, nb);
        }

        const uint32_t tb = sb + (uint32_t)buf * STAGE_B;
#pragma unroll
        for (int k16 = 0; k16 < 4; k16++) {
            const int cb = k16 * 2 + (lane >> 4);
            uint32_t af[4][4];
#pragma unroll
            for (int mb = 0; mb < 4; mb++) {
                const int R = ar + mb * 16;
                ldm4(af[mb], tb + 0 * TILE_B + (uint32_t)(R * 128 + ((cb ^ (R & 7)) << 4)));
            }
            uint32_t bf[2][4];
#pragma unroll
            for (int q = 0; q < 2; q++) {
                const int R = br + q * 16;
                ldm4(bf[q], tb + 1 * TILE_B + (uint32_t)(R * 128 + ((cb ^ (R & 7)) << 4)));
            }
#pragma unroll
            for (int mb = 0; mb < 4; mb++)
#pragma unroll
                for (int q = 0; q < 2; q++) {
                    mma16816h(acc[mb][2 * q],     af[mb], bf[q][0], bf[q][2]);
                    mma16816h(acc[mb][2 * q + 1], af[mb], bf[q][1], bf[q][3]);
                }
        }
        if (++buf == NSTAGE) buf = 0;
    }

    // ---- epilogue ----
    const int g  = lane >> 2;
    const int tg = lane & 3;
    if (C) {
        C += blockIdx.z * cZ;
#pragma unroll
        for (int mb = 0; mb < 4; mb++) {
            const int row = m0 + wm * 64 + mb * 16 + g;
#pragma unroll
            for (int nb = 0; nb < 4; nb++) {
                const int col = n0 + wn * 32 + nb * 8 + tg * 2;
                float2 v0, v1;
                v0.x = acc[mb][nb][0] * scale; v0.y = acc[mb][nb][1] * scale;
                v1.x = acc[mb][nb][2] * scale; v1.y = acc[mb][nb][3] * scale;
                *(float2*)(C + (size_t)row * ldc + col)       = v0;
                *(float2*)(C + (size_t)(row + 8) * ldc + col) = v1;
            }
        }
    } else {
        Ch += blockIdx.z * cZ;
#pragma unroll
        for (int mb = 0; mb < 4; mb++) {
            const int row = m0 + wm * 64 + mb * 16 + g;
#pragma unroll
            for (int nb = 0; nb < 4; nb++) {
                const int col = n0 + wn * 32 + nb * 8 + tg * 2;
                __half2 h0 = __floats2half2_rn(acc[mb][nb][0] * scale, acc[mb][nb][1] * scale);
                __half2 h1 = __floats2half2_rn(acc[mb][nb][2] * scale, acc[mb][nb][3] * scale);
                *(__half2*)(Ch + (size_t)row * ldc + col)       = h0;
                *(__half2*)(Ch + (size_t)(row + 8) * ldc + col) = h1;
            }
        }
    }
}

// =============================================================================
// convert kernel: fp32 -> fp16
// =============================================================================
__global__ void __launch_bounds__(256) cvt16_kernel(
    const float* __restrict__ src, __half* __restrict__ dst, long long n4)
{
    const long long i = (long long)blockIdx.x * 256 + threadIdx.x;
    if (i >= n4) return;
    float4 v = ((const float4*)src)[i];
    __half2 h0 = __floats2half2_rn(v.x, v.y);
    __half2 h1 = __floats2half2_rn(v.z, v.w);
    uint2 o;
    o.x = *(uint32_t*)&h0;
    o.y = *(uint32_t*)&h1;
    ((uint2*)dst)[i] = o;
}

// =============================================================================
// RoPE + convert: reads q,k from qkv fp32, writes q16/k16 fp16
// =============================================================================
__global__ void __launch_bounds__(1024) rope_kernel(
    const float* __restrict__ qkv,
    __half* __restrict__ q16, __half* __restrict__ k16)
{
    __shared__ float s_inv[64];
    const int s = blockIdx.x;
    const int t = threadIdx.x;
    if (t < 64) s_inv[t] = (float)pow(10000.0, -(double)(2 * t) / 128.0);
    __syncthreads();

    const int h = t >> 6;
    const int j = t & 63;
    const float ang = (float)((double)s * (double)s_inv[j]);
    float sn, cs;
    sincosf(ang, &sn, &cs);

    const float* q = qkv + (size_t)s * E3 + h * HD;
    const float* k = q + D_MODEL;
    const size_t ob = (size_t)s * D_MODEL + h * HD;

    const float q1 = q[j], q2 = q[j + 64];
    const float k1 = k[j], k2 = k[j + 64];
    q16[ob + j]      = __float2half_rn(q1 * cs - q2 * sn);
    q16[ob + j + 64] = __float2half_rn(q2 * cs + q1 * sn);
    k16[ob + j]      = __float2half_rn(k1 * cs - k2 * sn);
    k16[ob + j + 64] = __float2half_rn(k2 * cs + k1 * sn);
}

// =============================================================================
// V transpose + convert: vt[c][s] = qkv[s][2D + c]
// =============================================================================
__global__ void __launch_bounds__(256) vtrans_kernel(
    const float* __restrict__ qkv, __half* __restrict__ vt16)
{
    __shared__ float tile[32][33];
    const int c0 = blockIdx.x * 32;
    const int s0 = blockIdx.y * 32;
    const int tx = threadIdx.x & 31;
    const int ty = threadIdx.x >> 5;

#pragma unroll
    for (int r = ty; r < 32; r += 8)
        tile[r][tx] = qkv[(size_t)(s0 + r) * E3 + 2 * D_MODEL + c0 + tx];
    __syncthreads();
#pragma unroll
    for (int r = ty; r < 32; r += 8)
        vt16[(size_t)(c0 + r) * S_LEN + s0 + tx] = __float2half_rn(tile[tx][r]);
}

// =============================================================================
// softmax: fp32 scores row -> fp16 probabilities
// =============================================================================
__global__ void __launch_bounds__(256) softmax_kernel(
    const float* __restrict__ scores, __half* __restrict__ p16)
{
    const long long row = blockIdx.x;
    const float* p = scores + row * S_LEN;
    const int t = threadIdx.x;
    const int lane = t & 31, warp = t >> 5;

    __shared__ float red[8];

    float4 u0 = ((const float4*)p)[t * 2];
    float4 u1 = ((const float4*)p)[t * 2 + 1];
    float v[8] = {u0.x, u0.y, u0.z, u0.w, u1.x, u1.y, u1.z, u1.w};

    float mx = -INFINITY;
#pragma unroll
    for (int i = 0; i < 8; i++) mx = fmaxf(mx, v[i]);
#pragma unroll
    for (int o = 16; o; o >>= 1) mx = fmaxf(mx, __shfl_xor_sync(0xffffffffu, mx, o));
    if (lane == 0) red[warp] = mx;
    __syncthreads();
    if (t < 32) {
        float x = (t < 8) ? red[t] : -INFINITY;
#pragma unroll
        for (int o = 4; o; o >>= 1) x = fmaxf(x, __shfl_xor_sync(0xffffffffu, x, o));
        if (t == 0) red[0] = x;
    }
    __syncthreads();
    mx = red[0];
    __syncthreads();

    float sum = 0.0f;
#pragma unroll
    for (int i = 0; i < 8; i++) {
        v[i] = __expf(v[i] - mx);
        sum += v[i];
    }
#pragma unroll
    for (int o = 16; o; o >>= 1) sum += __shfl_xor_sync(0xffffffffu, sum, o);
    if (lane == 0) red[warp] = sum;
    __syncthreads();
    if (t < 32) {
        float x = (t < 8) ? red[t] : 0.0f;
#pragma unroll
        for (int o = 4; o; o >>= 1) x += __shfl_xor_sync(0xffffffffu, x, o);
        if (t == 0) red[0] = x;
    }
    __syncthreads();
    const float r = 1.0f / red[0];

    __half2 h0 = __floats2half2_rn(v[0] * r, v[1] * r);
    __half2 h1 = __floats2half2_rn(v[2] * r, v[3] * r);
    __half2 h2 = __floats2half2_rn(v[4] * r, v[5] * r);
    __half2 h3 = __floats2half2_rn(v[6] * r, v[7] * r);
    uint4 o;
    o.x = *(uint32_t*)&h0; o.y = *(uint32_t*)&h1;
    o.z = *(uint32_t*)&h2; o.w = *(uint32_t*)&h3;
    *(uint4*)(p16 + (size_t)row * S_LEN + (size_t)t * 8) = o;
}

// =============================================================================
// launch
// =============================================================================
extern "C" void kernel_launch(void* const* d_in, const int* in_sizes, int n_in,
                              void* d_out, int out_size)
{
    (void)in_sizes; (void)n_in; (void)out_size;
    const float* x     = (const float*)d_in[0];   // [1, 2048, 2048]
    const float* w_qkv = (const float*)d_in[1];   // [6144, 2048]
    const float* w_out = (const float*)d_in[2];   // [2048, 2048]
    float* out = (float*)d_out;                   // [1, 2048, 2048]

    float *qkv, *scores;
    cudaGetSymbolAddress((void**)&qkv,    g_qkv);
    cudaGetSymbolAddress((void**)&scores, g_scores);
    __half *x16, *wq16, *wo16, *q16, *k16, *vt16, *at16, *p16;
    cudaGetSymbolAddress((void**)&x16,  g_x16);
    cudaGetSymbolAddress((void**)&wq16, g_wq16);
    cudaGetSymbolAddress((void**)&wo16, g_wo16);
    cudaGetSymbolAddress((void**)&q16,  g_q16);
    cudaGetSymbolAddress((void**)&k16,  g_k16);
    cudaGetSymbolAddress((void**)&vt16, g_vt16);
    cudaGetSymbolAddress((void**)&at16, g_at16);
    cudaGetSymbolAddress((void**)&p16,  g_p16);

    cudaFuncSetAttribute(gemm_tc_kernel, cudaFuncAttributeMaxDynamicSharedMemorySize, GEMM_SMEM);

    const float scale = 0.08838834764831845f;  // 1/sqrt(128)

    // 0) convert inputs to fp16
    {
        long long n4;
        n4 = (long long)S_LEN * D_MODEL / 4;
        cvt16_kernel<<<(unsigned)((n4 + 255) / 256), 256>>>(x, x16, n4);
        n4 = (long long)E3 * D_MODEL / 4;
        cvt16_kernel<<<(unsigned)((n4 + 255) / 256), 256>>>(w_qkv, wq16, n4);
        n4 = (long long)D_MODEL * D_MODEL / 4;
        cvt16_kernel<<<(unsigned)((n4 + 255) / 256), 256>>>(w_out, wo16, n4);
    }

    // 1) QKV projection (fp32 out)
    {
        dim3 grid(E3 / 128, S_LEN / 128, 1);
        gemm_tc_kernel<<<grid, 256, GEMM_SMEM>>>(x16, wq16, qkv, nullptr,
                                                 D_MODEL, D_MODEL, D_MODEL, E3,
                                                 0, 0, 0, 1.0f);
    }

    // 2) RoPE -> q16,k16 ; transpose v -> vt16
    rope_kernel<<<S_LEN, 1024>>>(qkv, q16, k16);
    {
        dim3 grid(D_MODEL / 32, S_LEN / 32, 1);
        vtrans_kernel<<<grid, 256>>>(qkv, vt16);
    }

    // 3) scores (fp32 out, scaled)
    {
        dim3 grid(S_LEN / 128, S_LEN / 128, N_HEADS);
        gemm_tc_kernel<<<grid, 256, GEMM_SMEM>>>(q16, k16, scores, nullptr,
                                                 HD, D_MODEL, D_MODEL, S_LEN,
                                                 HD, HD, (long long)S_LEN * S_LEN, scale);
    }

    // 4) softmax -> p16
    softmax_kernel<<<N_HEADS * S_LEN, 256>>>(scores, p16);

    // 5) PV -> at16 (fp16 out)
    {
        dim3 grid(1, S_LEN / 128, N_HEADS);
        gemm_tc_kernel<<<grid, 256, GEMM_SMEM>>>(p16, vt16, nullptr, at16,
                                                 S_LEN, S_LEN, S_LEN, D_MODEL,
                                                 (long long)S_LEN * S_LEN,
                                                 (long long)HD * S_LEN,
                                                 (long long)HD, 1.0f);
    }

    // 6) out projection (fp32 out)
    {
        dim3 grid(D_MODEL / 128, S_LEN / 128, 1);
        gemm_tc_kernel<<<grid, 256, GEMM_SMEM>>>(at16, wo16, out, nullptr,
                                                 D_MODEL, D_MODEL, D_MODEL, D_MODEL,
                                                 0, 0, 0, 1.0f);
    }
}

// round 11
// speedup vs baseline: 2.6932x; 1.1875x over previous
#include <cuda_runtime.h>
#include <cuda_fp16.h>
#include <math.h>
#include <stdint.h>

#define S_LEN 2048
#define D_MODEL 2048
#define N_HEADS 16
#define HD 128
#define E3 (3 * D_MODEL)   // 6144

// softmax scale folded with log2(e): softmax(s*scale) == exp2-softmax(s*scale*log2e)
#define SCALE_LOG2E (0.08838834764831845f * 1.4426950408889634f)

// ---------------- scratch (static device globals; no allocations) -------------
__device__ float g_qkv[(size_t)S_LEN * E3];                      // fp32 qkv

__device__ __half g_x16[(size_t)S_LEN * D_MODEL];
__device__ __half g_wq16[(size_t)E3 * D_MODEL];
__device__ __half g_wo16[(size_t)D_MODEL * D_MODEL];
__device__ __half g_q16[(size_t)S_LEN * D_MODEL];    // rope'd, pre-scaled by SCALE_LOG2E
__device__ __half g_k16[(size_t)S_LEN * D_MODEL];    // rope'd
__device__ __half g_vt16[(size_t)D_MODEL * S_LEN];   // V transposed: [hd_global][s]
__device__ __half g_at16[(size_t)S_LEN * D_MODEL];   // attention output fp16

// =============================================================================
// helpers (base-ISA only: mma.sync / ldmatrix / cp.async)
// =============================================================================
__device__ __forceinline__ uint32_t smem_u32(const void* p) {
    uint32_t a;
    asm("{ .reg .u64 t; cvta.to.shared.u64 t, %1; cvt.u32.u64 %0, t; }" : "=r"(a) : "l"(p));
    return a;
}
__device__ __forceinline__ void cp16(uint32_t dst, const void* src) {
    asm volatile("cp.async.cg.shared.global [%0], [%1], 16;" :: "r"(dst), "l"(src));
}
#define CP_COMMIT() asm volatile("cp.async.commit_group;" ::: "memory")
#define CP_WAIT(n)  asm volatile("cp.async.wait_group %0;" :: "n"(n) : "memory")

__device__ __forceinline__ void ldm4(uint32_t* r, uint32_t addr) {
    asm volatile("ldmatrix.sync.aligned.m8n8.x4.shared.b16 {%0,%1,%2,%3}, [%4];"
                 : "=r"(r[0]), "=r"(r[1]), "=r"(r[2]), "=r"(r[3]) : "r"(addr));
}
__device__ __forceinline__ void mma16816h(float* d, const uint32_t* a, uint32_t b0, uint32_t b1) {
    asm volatile(
        "mma.sync.aligned.m16n8k16.row.col.f32.f16.f16.f32 "
        "{%0,%1,%2,%3}, {%4,%5,%6,%7}, {%8,%9}, {%0,%1,%2,%3};"
        : "+f"(d[0]), "+f"(d[1]), "+f"(d[2]), "+f"(d[3])
        : "r"(a[0]), "r"(a[1]), "r"(a[2]), "r"(a[3]), "r"(b0), "r"(b1));
}
__device__ __forceinline__ uint32_t h2pack(float a, float b) {
    __half2 h = __floats2half2_rn(a, b);
    return *(uint32_t*)&h;
}

// =============================================================================
// fp16 NT GEMM on HMMA: C[m,n] = scale * sum_k A[m,k]*B[n,k]  (fp32 accum)
// CTA tile 128x128, K-tile 64, 4-stage cp.async pipeline, 256 threads,
// 8 warps as 2(m) x 4(n): warp tile 64x32.
// =============================================================================
#define TILE_B 16384                 // 128 rows * 64 fp16 * 2B = 128B rows
#define STAGE_B (2 * TILE_B)         // A, B
#define NSTAGE 4
#define GEMM_SMEM (NSTAGE * STAGE_B) // 128 KB

__global__ void __launch_bounds__(256, 1) gemm_tc_kernel(
    const __half* __restrict__ A, const __half* __restrict__ B,
    float* __restrict__ C,
    int K, int lda, int ldb, int ldc, float scale)
{
    extern __shared__ __align__(128) char smem[];
    const uint32_t sb = smem_u32(smem);
    const int tid = threadIdx.x;
    const int lane = tid & 31;
    const int wid = tid >> 5;
    const int wm = wid & 1;
    const int wn = wid >> 1;

    const int m0 = blockIdx.y * 128;
    const int n0 = blockIdx.x * 128;

    float acc[4][4][4];
#pragma unroll
    for (int a = 0; a < 4; a++)
#pragma unroll
        for (int b = 0; b < 4; b++)
#pragma unroll
            for (int c = 0; c < 4; c++) acc[a][b][c] = 0.0f;

    const int nt = K / 64;

    auto load_stage = [&](int t, int buf) {
        const uint32_t base = sb + (uint32_t)buf * STAGE_B;
#pragma unroll
        for (int i = 0; i < 4; i++) {
            const int cid = tid + 256 * i;
            const int row = cid >> 3;
            const int c   = cid & 7;
            const uint32_t phys = (uint32_t)(row * 128 + ((c ^ (row & 7)) << 4));
            cp16(base + 0 * TILE_B + phys, A + (size_t)(m0 + row) * lda + (size_t)t * 64 + c * 8);
            cp16(base + 1 * TILE_B + phys, B + (size_t)(n0 + row) * ldb + (size_t)t * 64 + c * 8);
        }
        CP_COMMIT();
    };

    load_stage(0, 0);
    if (nt > 1) load_stage(1, 1);
    if (nt > 2) load_stage(2, 2);

    const int ar = wm * 64 + (lane & 15);
    const int br = wn * 32 + (lane & 15);

    int buf = 0;
    for (int t = 0; t < nt; t++) {
        if (t + 1 < nt) {
            if (t + 2 < nt) { CP_WAIT(2); } else { CP_WAIT(1); }
        } else {
            CP_WAIT(0);
        }
        __syncthreads();

        if (t + 3 < nt) {
            int nb = buf + 3; if (nb >= NSTAGE) nb -= NSTAGE;
            load_stage(t + 3, nb);
        }

        const uint32_t tb = sb + (uint32_t)buf * STAGE_B;
#pragma unroll
        for (int k16 = 0; k16 < 4; k16++) {
            const int cb = k16 * 2 + (lane >> 4);
            uint32_t af[4][4];
#pragma unroll
            for (int mb = 0; mb < 4; mb++) {
                const int R = ar + mb * 16;
                ldm4(af[mb], tb + 0 * TILE_B + (uint32_t)(R * 128 + ((cb ^ (R & 7)) << 4)));
            }
            uint32_t bf[2][4];
#pragma unroll
            for (int q = 0; q < 2; q++) {
                const int R = br + q * 16;
                ldm4(bf[q], tb + 1 * TILE_B + (uint32_t)(R * 128 + ((cb ^ (R & 7)) << 4)));
            }
#pragma unroll
            for (int mb = 0; mb < 4; mb++)
#pragma unroll
                for (int q = 0; q < 2; q++) {
                    mma16816h(acc[mb][2 * q],     af[mb], bf[q][0], bf[q][2]);
                    mma16816h(acc[mb][2 * q + 1], af[mb], bf[q][1], bf[q][3]);
                }
        }
        if (++buf == NSTAGE) buf = 0;
    }

    const int g  = lane >> 2;
    const int tg = lane & 3;
#pragma unroll
    for (int mb = 0; mb < 4; mb++) {
        const int row = m0 + wm * 64 + mb * 16 + g;
#pragma unroll
        for (int nb = 0; nb < 4; nb++) {
            const int col = n0 + wn * 32 + nb * 8 + tg * 2;
            float2 v0, v1;
            v0.x = acc[mb][nb][0] * scale; v0.y = acc[mb][nb][1] * scale;
            v1.x = acc[mb][nb][2] * scale; v1.y = acc[mb][nb][3] * scale;
            *(float2*)(C + (size_t)row * ldc + col)       = v0;
            *(float2*)(C + (size_t)(row + 8) * ldc + col) = v1;
        }
    }
}

// =============================================================================
// flash attention: one CTA = (head, 128-row q tile).
// S = Q·K^T in exp2-space (q16 pre-scaled), online softmax, O += P·V.
// 256 threads, 8 warps; warp owns 16 q rows x all 128 kv cols.
// Tiles in smem are 128 rows x 256B (128 fp16), chunk swizzle c^((row&7)<<1).
// =============================================================================
#define FL_TILE_B 32768              // 128 * 256B
#define FL_Q_OFF 0
#define FL_S_OFF 32768
#define FL_STAGE_B (2 * FL_TILE_B)   // K tile + Vt tile
#define FL_NKV 16                    // 2048 / 128
#define FLASH_SMEM (FL_S_OFF + 3 * FL_STAGE_B)   // 32KB + 192KB = 224KB

__device__ __forceinline__ uint32_t fl_phys(int row, int c) {
    return (uint32_t)(row * 256 + ((c ^ ((row & 7) << 1)) << 4));
}

__global__ void __launch_bounds__(256, 1) flash_kernel(
    const __half* __restrict__ q16, const __half* __restrict__ k16,
    const __half* __restrict__ vt16, __half* __restrict__ at16)
{
    extern __shared__ __align__(128) char smem[];
    const uint32_t sb = smem_u32(smem);
    const int tid = threadIdx.x;
    const int lane = tid & 31;
    const int wid = tid >> 5;
    const int h = blockIdx.y;
    const int q0 = blockIdx.x * 128;

    // ---- load Q once (group shared with first KV stage) ----
#pragma unroll
    for (int i = 0; i < 8; i++) {
        const int cid = tid + 256 * i;      // 0..2047
        const int row = cid >> 4;
        const int c   = cid & 15;
        cp16(sb + FL_Q_OFF + fl_phys(row, c),
             q16 + (size_t)(q0 + row) * D_MODEL + h * HD + c * 8);
    }
    auto load_kv = [&](int j, int buf) {
        const uint32_t base = sb + FL_S_OFF + (uint32_t)buf * FL_STAGE_B;
#pragma unroll
        for (int i = 0; i < 8; i++) {
            const int cid = tid + 256 * i;
            const int row = cid >> 4;
            const int c   = cid & 15;
            cp16(base + fl_phys(row, c),
                 k16 + (size_t)(j * 128 + row) * D_MODEL + h * HD + c * 8);
            cp16(base + FL_TILE_B + fl_phys(row, c),
                 vt16 + (size_t)(h * HD + row) * S_LEN + j * 128 + c * 8);
        }
        CP_COMMIT();
    };
    load_kv(0, 0);   // commit covers Q too
    load_kv(1, 1);

    float o[16][4];
#pragma unroll
    for (int i = 0; i < 16; i++)
#pragma unroll
        for (int c = 0; c < 4; c++) o[i][c] = 0.0f;
    float m0 = -INFINITY, m1 = -INFINITY, l0 = 0.0f, l1 = 0.0f;

    const int arow = wid * 16 + (lane & 15);
    const int nrow = lane & 15;

    for (int j = 0; j < FL_NKV; j++) {
        if (j + 1 < FL_NKV) { CP_WAIT(1); } else { CP_WAIT(0); }
        __syncthreads();
        if (j + 2 < FL_NKV) {
            int nb = j + 2; load_kv(nb, nb % 3);
        }
        const uint32_t kb = sb + FL_S_OFF + (uint32_t)(j % 3) * FL_STAGE_B;

        // ---- S = Q·K^T (16 x 128 per warp), fp32 ----
        float s[16][4];
#pragma unroll
        for (int i = 0; i < 16; i++)
#pragma unroll
            for (int c = 0; c < 4; c++) s[i][c] = 0.0f;

#pragma unroll
        for (int kk = 0; kk < 8; kk++) {
            const int cb = kk * 2 + (lane >> 4);
            uint32_t af[4];
            ldm4(af, sb + FL_Q_OFF + fl_phys(arow, cb));
            uint32_t bf[4];
#pragma unroll
            for (int t = 0; t < 8; t++) {
                ldm4(bf, kb + fl_phys(t * 16 + nrow, cb));
                mma16816h(s[2 * t],     af, bf[0], bf[2]);
                mma16816h(s[2 * t + 1], af, bf[1], bf[3]);
            }
        }

        // ---- online softmax (exp2 space) ----
        float mj0 = -INFINITY, mj1 = -INFINITY;
#pragma unroll
        for (int i = 0; i < 16; i++) {
            mj0 = fmaxf(mj0, fmaxf(s[i][0], s[i][1]));
            mj1 = fmaxf(mj1, fmaxf(s[i][2], s[i][3]));
        }
        mj0 = fmaxf(mj0, __shfl_xor_sync(0xffffffffu, mj0, 1));
        mj0 = fmaxf(mj0, __shfl_xor_sync(0xffffffffu, mj0, 2));
        mj1 = fmaxf(mj1, __shfl_xor_sync(0xffffffffu, mj1, 1));
        mj1 = fmaxf(mj1, __shfl_xor_sync(0xffffffffu, mj1, 2));
        const float mn0 = fmaxf(m0, mj0);
        const float mn1 = fmaxf(m1, mj1);
        const float a0 = exp2f(m0 - mn0);
        const float a1 = exp2f(m1 - mn1);
        m0 = mn0; m1 = mn1;

        float sum0 = 0.0f, sum1 = 0.0f;
        uint32_t pa[8][4];
#pragma unroll
        for (int t = 0; t < 8; t++) {
            const float e00 = exp2f(s[2 * t][0] - m0),     e01 = exp2f(s[2 * t][1] - m0);
            const float e02 = exp2f(s[2 * t][2] - m1),     e03 = exp2f(s[2 * t][3] - m1);
            const float e10 = exp2f(s[2 * t + 1][0] - m0), e11 = exp2f(s[2 * t + 1][1] - m0);
            const float e12 = exp2f(s[2 * t + 1][2] - m1), e13 = exp2f(s[2 * t + 1][3] - m1);
            sum0 += (e00 + e01) + (e10 + e11);
            sum1 += (e02 + e03) + (e12 + e13);
            pa[t][0] = h2pack(e00, e01);
            pa[t][1] = h2pack(e02, e03);
            pa[t][2] = h2pack(e10, e11);
            pa[t][3] = h2pack(e12, e13);
        }
        // FIX (R10 bug): reduce row-sums across the 4 threads of each quad.
        // A q-row's 128 kv columns live in 4 threads (tg = lane&3); l0/l1 must
        // be the FULL row sum before normalization.
        sum0 += __shfl_xor_sync(0xffffffffu, sum0, 1);
        sum0 += __shfl_xor_sync(0xffffffffu, sum0, 2);
        sum1 += __shfl_xor_sync(0xffffffffu, sum1, 1);
        sum1 += __shfl_xor_sync(0xffffffffu, sum1, 2);
        l0 = l0 * a0 + sum0;
        l1 = l1 * a1 + sum1;
#pragma unroll
        for (int i = 0; i < 16; i++) {
            o[i][0] *= a0; o[i][1] *= a0;
            o[i][2] *= a1; o[i][3] *= a1;
        }

        // ---- O += P·V  (B = Vt tile: [hd][kv]) ----
#pragma unroll
        for (int t = 0; t < 8; t++) {
            const int cbv = t * 2 + (lane >> 4);
            uint32_t vf[4];
#pragma unroll
            for (int u = 0; u < 8; u++) {
                ldm4(vf, kb + FL_TILE_B + fl_phys(u * 16 + nrow, cbv));
                mma16816h(o[2 * u],     pa[t], vf[0], vf[2]);
                mma16816h(o[2 * u + 1], pa[t], vf[1], vf[3]);
            }
        }
    }

    // ---- epilogue: normalize and store fp16 ----
    const int g  = lane >> 2;
    const int tg = lane & 3;
    const float r0 = 1.0f / l0;
    const float r1 = 1.0f / l1;
    const size_t row0 = (size_t)(q0 + wid * 16 + g) * D_MODEL + h * HD;
    const size_t row1 = row0 + (size_t)8 * D_MODEL;
#pragma unroll
    for (int nb = 0; nb < 16; nb++) {
        const int col = nb * 8 + tg * 2;
        *(uint32_t*)(at16 + row0 + col) = h2pack(o[nb][0] * r0, o[nb][1] * r0);
        *(uint32_t*)(at16 + row1 + col) = h2pack(o[nb][2] * r1, o[nb][3] * r1);
    }
}

// =============================================================================
// convert kernel: fp32 -> fp16
// =============================================================================
__global__ void __launch_bounds__(256) cvt16_kernel(
    const float* __restrict__ src, __half* __restrict__ dst, long long n4)
{
    const long long i = (long long)blockIdx.x * 256 + threadIdx.x;
    if (i >= n4) return;
    float4 v = ((const float4*)src)[i];
    uint2 o;
    o.x = h2pack(v.x, v.y);
    o.y = h2pack(v.z, v.w);
    ((uint2*)dst)[i] = o;
}

// =============================================================================
// RoPE + convert: q gets pre-scaled by SCALE_LOG2E for exp2-space softmax
// =============================================================================
__global__ void __launch_bounds__(1024) rope_kernel(
    const float* __restrict__ qkv,
    __half* __restrict__ q16, __half* __restrict__ k16)
{
    __shared__ float s_inv[64];
    const int s = blockIdx.x;
    const int t = threadIdx.x;
    if (t < 64) s_inv[t] = (float)pow(10000.0, -(double)(2 * t) / 128.0);
    __syncthreads();

    const int h = t >> 6;
    const int j = t & 63;
    const float ang = (float)((double)s * (double)s_inv[j]);
    float sn, cs;
    sincosf(ang, &sn, &cs);

    const float* q = qkv + (size_t)s * E3 + h * HD;
    const float* k = q + D_MODEL;
    const size_t ob = (size_t)s * D_MODEL + h * HD;

    const float q1 = q[j], q2 = q[j + 64];
    const float k1 = k[j], k2 = k[j + 64];
    q16[ob + j]      = __float2half_rn((q1 * cs - q2 * sn) * SCALE_LOG2E);
    q16[ob + j + 64] = __float2half_rn((q2 * cs + q1 * sn) * SCALE_LOG2E);
    k16[ob + j]      = __float2half_rn(k1 * cs - k2 * sn);
    k16[ob + j + 64] = __float2half_rn(k2 * cs + k1 * sn);
}

// =============================================================================
// V transpose + convert: vt[c][s] = qkv[s][2D + c]
// =============================================================================
__global__ void __launch_bounds__(256) vtrans_kernel(
    const float* __restrict__ qkv, __half* __restrict__ vt16)
{
    __shared__ float tile[32][33];
    const int c0 = blockIdx.x * 32;
    const int s0 = blockIdx.y * 32;
    const int tx = threadIdx.x & 31;
    const int ty = threadIdx.x >> 5;

#pragma unroll
    for (int r = ty; r < 32; r += 8)
        tile[r][tx] = qkv[(size_t)(s0 + r) * E3 + 2 * D_MODEL + c0 + tx];
    __syncthreads();
#pragma unroll
    for (int r = ty; r < 32; r += 8)
        vt16[(size_t)(c0 + r) * S_LEN + s0 + tx] = __float2half_rn(tile[tx][r]);
}

// =============================================================================
// launch
// =============================================================================
extern "C" void kernel_launch(void* const* d_in, const int* in_sizes, int n_in,
                              void* d_out, int out_size)
{
    (void)in_sizes; (void)n_in; (void)out_size;
    const float* x     = (const float*)d_in[0];   // [1, 2048, 2048]
    const float* w_qkv = (const float*)d_in[1];   // [6144, 2048]
    const float* w_out = (const float*)d_in[2];   // [2048, 2048]
    float* out = (float*)d_out;                   // [1, 2048, 2048]

    float* qkv;
    cudaGetSymbolAddress((void**)&qkv, g_qkv);
    __half *x16, *wq16, *wo16, *q16, *k16, *vt16, *at16;
    cudaGetSymbolAddress((void**)&x16,  g_x16);
    cudaGetSymbolAddress((void**)&wq16, g_wq16);
    cudaGetSymbolAddress((void**)&wo16, g_wo16);
    cudaGetSymbolAddress((void**)&q16,  g_q16);
    cudaGetSymbolAddress((void**)&k16,  g_k16);
    cudaGetSymbolAddress((void**)&vt16, g_vt16);
    cudaGetSymbolAddress((void**)&at16, g_at16);

    cudaFuncSetAttribute(gemm_tc_kernel, cudaFuncAttributeMaxDynamicSharedMemorySize, GEMM_SMEM);
    cudaFuncSetAttribute(flash_kernel,   cudaFuncAttributeMaxDynamicSharedMemorySize, FLASH_SMEM);

    // 0) convert inputs to fp16
    {
        long long n4;
        n4 = (long long)S_LEN * D_MODEL / 4;
        cvt16_kernel<<<(unsigned)((n4 + 255) / 256), 256>>>(x, x16, n4);
        n4 = (long long)E3 * D_MODEL / 4;
        cvt16_kernel<<<(unsigned)((n4 + 255) / 256), 256>>>(w_qkv, wq16, n4);
        n4 = (long long)D_MODEL * D_MODEL / 4;
        cvt16_kernel<<<(unsigned)((n4 + 255) / 256), 256>>>(w_out, wo16, n4);
    }

    // 1) QKV projection (fp32 out)
    {
        dim3 grid(E3 / 128, S_LEN / 128, 1);
        gemm_tc_kernel<<<grid, 256, GEMM_SMEM>>>(x16, wq16, qkv,
                                                 D_MODEL, D_MODEL, D_MODEL, E3, 1.0f);
    }

    // 2) RoPE -> q16 (pre-scaled), k16 ; transpose v -> vt16
    rope_kernel<<<S_LEN, 1024>>>(qkv, q16, k16);
    {
        dim3 grid(D_MODEL / 32, S_LEN / 32, 1);
        vtrans_kernel<<<grid, 256>>>(qkv, vt16);
    }

    // 3) flash attention: scores + softmax + PV fused -> at16
    {
        dim3 grid(S_LEN / 128, N_HEADS, 1);
        flash_kernel<<<grid, 256, FLASH_SMEM>>>(q16, k16, vt16, at16);
    }

    // 4) out projection (fp32 out)
    {
        dim3 grid(D_MODEL / 128, S_LEN / 128, 1);
        gemm_tc_kernel<<<grid, 256, GEMM_SMEM>>>(at16, wo16, out,
                                                 D_MODEL, D_MODEL, D_MODEL, D_MODEL, 1.0f);
    }
}

// round 12
// speedup vs baseline: 2.8858x; 1.0715x over previous
#include <cuda_runtime.h>
#include <cuda_fp16.h>
#include <math.h>
#include <stdint.h>

#define S_LEN 2048
#define D_MODEL 2048
#define N_HEADS 16
#define HD 128
#define E3 (3 * D_MODEL)   // 6144

// softmax scale folded with log2(e): softmax(s*scale) == exp2-softmax(s*scale*log2e)
#define SCALE_LOG2E (0.08838834764831845f * 1.4426950408889634f)

// ---------------- scratch (static device globals; no allocations) -------------
__device__ float g_qkv[(size_t)S_LEN * E3];                      // fp32 qkv

__device__ __half g_x16[(size_t)S_LEN * D_MODEL];
__device__ __half g_wq16[(size_t)E3 * D_MODEL];
__device__ __half g_wo16[(size_t)D_MODEL * D_MODEL];
__device__ __half g_q16[(size_t)S_LEN * D_MODEL];    // rope'd, pre-scaled by SCALE_LOG2E
__device__ __half g_k16[(size_t)S_LEN * D_MODEL];    // rope'd
__device__ __half g_vt16[(size_t)D_MODEL * S_LEN];   // V transposed: [hd_global][s]
__device__ __half g_at16[(size_t)S_LEN * D_MODEL];   // attention output fp16

// =============================================================================
// helpers (base-ISA only: mma.sync / ldmatrix / cp.async)
// =============================================================================
__device__ __forceinline__ uint32_t smem_u32(const void* p) {
    uint32_t a;
    asm("{ .reg .u64 t; cvta.to.shared.u64 t, %1; cvt.u32.u64 %0, t; }" : "=r"(a) : "l"(p));
    return a;
}
__device__ __forceinline__ void cp16(uint32_t dst, const void* src) {
    asm volatile("cp.async.cg.shared.global [%0], [%1], 16;" :: "r"(dst), "l"(src));
}
#define CP_COMMIT() asm volatile("cp.async.commit_group;" ::: "memory")
#define CP_WAIT(n)  asm volatile("cp.async.wait_group %0;" :: "n"(n) : "memory")

__device__ __forceinline__ void ldm4(uint32_t* r, uint32_t addr) {
    asm volatile("ldmatrix.sync.aligned.m8n8.x4.shared.b16 {%0,%1,%2,%3}, [%4];"
                 : "=r"(r[0]), "=r"(r[1]), "=r"(r[2]), "=r"(r[3]) : "r"(addr));
}
__device__ __forceinline__ void mma16816h(float* d, const uint32_t* a, uint32_t b0, uint32_t b1) {
    asm volatile(
        "mma.sync.aligned.m16n8k16.row.col.f32.f16.f16.f32 "
        "{%0,%1,%2,%3}, {%4,%5,%6,%7}, {%8,%9}, {%0,%1,%2,%3};"
        : "+f"(d[0]), "+f"(d[1]), "+f"(d[2]), "+f"(d[3])
        : "r"(a[0]), "r"(a[1]), "r"(a[2]), "r"(a[3]), "r"(b0), "r"(b1));
}
__device__ __forceinline__ uint32_t h2pack(float a, float b) {
    __half2 h = __floats2half2_rn(a, b);
    return *(uint32_t*)&h;
}

// =============================================================================
// fp16 NT GEMM on HMMA: C[m,n] = scale * sum_k A[m,k]*B[n,k]  (fp32 accum)
// CTA tile 128x256, K-tile 64, 4-stage cp.async pipeline, 256 threads,
// 8 warps as 2(m) x 4(n): warp tile 64x64 (8 ldm4 -> 32 MMAs per k16).
// =============================================================================
#define TILE_A_B 16384               // A: 128 rows * 128B
#define TILE_B_B 32768               // B: 256 rows * 128B
#define STAGE_B (TILE_A_B + TILE_B_B)
#define NSTAGE 4
#define GEMM_SMEM (NSTAGE * STAGE_B) // 192 KB

__global__ void __launch_bounds__(256, 1) gemm_tc_kernel(
    const __half* __restrict__ A, const __half* __restrict__ B,
    float* __restrict__ C,
    int K, int lda, int ldb, int ldc, float scale)
{
    extern __shared__ __align__(128) char smem[];
    const uint32_t sb = smem_u32(smem);
    const int tid = threadIdx.x;
    const int lane = tid & 31;
    const int wid = tid >> 5;
    const int wm = wid & 1;           // m offset 64*wm
    const int wn = wid >> 1;          // n offset 64*wn (0..3)

    const int m0 = blockIdx.y * 128;
    const int n0 = blockIdx.x * 256;

    float acc[4][8][4];
#pragma unroll
    for (int a = 0; a < 4; a++)
#pragma unroll
        for (int b = 0; b < 8; b++)
#pragma unroll
            for (int c = 0; c < 4; c++) acc[a][b][c] = 0.0f;

    const int nt = K / 64;

    auto load_stage = [&](int t, int buf) {
        const uint32_t base = sb + (uint32_t)buf * STAGE_B;
        // A: 128 rows x 64 halves = 1024 16B chunks
#pragma unroll
        for (int i = 0; i < 4; i++) {
            const int cid = tid + 256 * i;
            const int row = cid >> 3;
            const int c   = cid & 7;
            const uint32_t phys = (uint32_t)(row * 128 + ((c ^ (row & 7)) << 4));
            cp16(base + phys, A + (size_t)(m0 + row) * lda + (size_t)t * 64 + c * 8);
        }
        // B: 256 rows x 64 halves = 2048 16B chunks
#pragma unroll
        for (int i = 0; i < 8; i++) {
            const int cid = tid + 256 * i;
            const int row = cid >> 3;          // 0..255
            const int c   = cid & 7;
            const uint32_t phys = (uint32_t)(row * 128 + ((c ^ (row & 7)) << 4));
            cp16(base + TILE_A_B + phys, B + (size_t)(n0 + row) * ldb + (size_t)t * 64 + c * 8);
        }
        CP_COMMIT();
    };

    load_stage(0, 0);
    if (nt > 1) load_stage(1, 1);
    if (nt > 2) load_stage(2, 2);

    const int ar = wm * 64 + (lane & 15);
    const int br = wn * 64 + (lane & 15);

    int buf = 0;
    for (int t = 0; t < nt; t++) {
        if (t + 1 < nt) {
            if (t + 2 < nt) { CP_WAIT(2); } else { CP_WAIT(1); }
        } else {
            CP_WAIT(0);
        }
        __syncthreads();

        if (t + 3 < nt) {
            int nb = buf + 3; if (nb >= NSTAGE) nb -= NSTAGE;
            load_stage(t + 3, nb);
        }

        const uint32_t tb = sb + (uint32_t)buf * STAGE_B;
#pragma unroll
        for (int k16 = 0; k16 < 4; k16++) {
            const int cb = k16 * 2 + (lane >> 4);
            uint32_t af[4][4];
#pragma unroll
            for (int mb = 0; mb < 4; mb++) {
                const int R = ar + mb * 16;
                ldm4(af[mb], tb + (uint32_t)(R * 128 + ((cb ^ (R & 7)) << 4)));
            }
            uint32_t bf[4][4];
#pragma unroll
            for (int q = 0; q < 4; q++) {
                const int R = br + q * 16;
                ldm4(bf[q], tb + TILE_A_B + (uint32_t)(R * 128 + ((cb ^ (R & 7)) << 4)));
            }
#pragma unroll
            for (int mb = 0; mb < 4; mb++)
#pragma unroll
                for (int q = 0; q < 4; q++) {
                    mma16816h(acc[mb][2 * q],     af[mb], bf[q][0], bf[q][2]);
                    mma16816h(acc[mb][2 * q + 1], af[mb], bf[q][1], bf[q][3]);
                }
        }
        if (++buf == NSTAGE) buf = 0;
    }

    const int g  = lane >> 2;
    const int tg = lane & 3;
#pragma unroll
    for (int mb = 0; mb < 4; mb++) {
        const int row = m0 + wm * 64 + mb * 16 + g;
#pragma unroll
        for (int nb = 0; nb < 8; nb++) {
            const int col = n0 + wn * 64 + nb * 8 + tg * 2;
            float2 v0, v1;
            v0.x = acc[mb][nb][0] * scale; v0.y = acc[mb][nb][1] * scale;
            v1.x = acc[mb][nb][2] * scale; v1.y = acc[mb][nb][3] * scale;
            *(float2*)(C + (size_t)row * ldc + col)       = v0;
            *(float2*)(C + (size_t)(row + 8) * ldc + col) = v1;
        }
    }
}

// =============================================================================
// flash attention: one CTA = (head, 128-row q tile).
// S = Q·K^T in exp2-space (q16 pre-scaled), online softmax, O += P·V.
// 256 threads, 8 warps; warp owns 16 q rows x all 128 kv cols.
// Q fragments cached in registers across all KV blocks.
// Tiles in smem are 128 rows x 256B (128 fp16), chunk swizzle c^((row&7)<<1).
// =============================================================================
#define FL_TILE_B 32768              // 128 * 256B
#define FL_Q_OFF 0
#define FL_S_OFF 32768
#define FL_STAGE_B (2 * FL_TILE_B)   // K tile + Vt tile
#define FL_NKV 16                    // 2048 / 128
#define FLASH_SMEM (FL_S_OFF + 3 * FL_STAGE_B)   // 32KB + 192KB = 224KB

__device__ __forceinline__ uint32_t fl_phys(int row, int c) {
    return (uint32_t)(row * 256 + ((c ^ ((row & 7) << 1)) << 4));
}

__global__ void __launch_bounds__(256, 1) flash_kernel(
    const __half* __restrict__ q16, const __half* __restrict__ k16,
    const __half* __restrict__ vt16, __half* __restrict__ at16)
{
    extern __shared__ __align__(128) char smem[];
    const uint32_t sb = smem_u32(smem);
    const int tid = threadIdx.x;
    const int lane = tid & 31;
    const int wid = tid >> 5;
    const int h = blockIdx.y;
    const int q0 = blockIdx.x * 128;

    // ---- load Q once (group shared with first KV stage) ----
#pragma unroll
    for (int i = 0; i < 8; i++) {
        const int cid = tid + 256 * i;      // 0..2047
        const int row = cid >> 4;
        const int c   = cid & 15;
        cp16(sb + FL_Q_OFF + fl_phys(row, c),
             q16 + (size_t)(q0 + row) * D_MODEL + h * HD + c * 8);
    }
    auto load_kv = [&](int j, int buf) {
        const uint32_t base = sb + FL_S_OFF + (uint32_t)buf * FL_STAGE_B;
#pragma unroll
        for (int i = 0; i < 8; i++) {
            const int cid = tid + 256 * i;
            const int row = cid >> 4;
            const int c   = cid & 15;
            cp16(base + fl_phys(row, c),
                 k16 + (size_t)(j * 128 + row) * D_MODEL + h * HD + c * 8);
            cp16(base + FL_TILE_B + fl_phys(row, c),
                 vt16 + (size_t)(h * HD + row) * S_LEN + j * 128 + c * 8);
        }
        CP_COMMIT();
    };
    load_kv(0, 0);   // commit covers Q too
    load_kv(1, 1);

    float o[16][4];
#pragma unroll
    for (int i = 0; i < 16; i++)
#pragma unroll
        for (int c = 0; c < 4; c++) o[i][c] = 0.0f;
    float m0 = -INFINITY, m1 = -INFINITY, l0 = 0.0f, l1 = 0.0f;

    const int arow = wid * 16 + (lane & 15);
    const int nrow = lane & 15;

    // ---- cache Q fragments in registers (valid for all KV blocks) ----
    CP_WAIT(1);          // group 0 (Q + kv0) resident
    __syncthreads();
    uint32_t qf[8][4];
#pragma unroll
    for (int kk = 0; kk < 8; kk++) {
        const int cb = kk * 2 + (lane >> 4);
        ldm4(qf[kk], sb + FL_Q_OFF + fl_phys(arow, cb));
    }

    for (int j = 0; j < FL_NKV; j++) {
        if (j + 1 < FL_NKV) { CP_WAIT(1); } else { CP_WAIT(0); }
        __syncthreads();
        if (j + 2 < FL_NKV) {
            int nb = j + 2; load_kv(nb, nb % 3);
        }
        const uint32_t kb = sb + FL_S_OFF + (uint32_t)(j % 3) * FL_STAGE_B;

        // ---- S = Q·K^T (16 x 128 per warp), fp32 ----
        float s[16][4];
#pragma unroll
        for (int i = 0; i < 16; i++)
#pragma unroll
            for (int c = 0; c < 4; c++) s[i][c] = 0.0f;

#pragma unroll
        for (int kk = 0; kk < 8; kk++) {
            const int cb = kk * 2 + (lane >> 4);
            uint32_t bf[4];
#pragma unroll
            for (int t = 0; t < 8; t++) {
                ldm4(bf, kb + fl_phys(t * 16 + nrow, cb));
                mma16816h(s[2 * t],     qf[kk], bf[0], bf[2]);
                mma16816h(s[2 * t + 1], qf[kk], bf[1], bf[3]);
            }
        }

        // ---- online softmax (exp2 space) ----
        float mj0 = -INFINITY, mj1 = -INFINITY;
#pragma unroll
        for (int i = 0; i < 16; i++) {
            mj0 = fmaxf(mj0, fmaxf(s[i][0], s[i][1]));
            mj1 = fmaxf(mj1, fmaxf(s[i][2], s[i][3]));
        }
        mj0 = fmaxf(mj0, __shfl_xor_sync(0xffffffffu, mj0, 1));
        mj0 = fmaxf(mj0, __shfl_xor_sync(0xffffffffu, mj0, 2));
        mj1 = fmaxf(mj1, __shfl_xor_sync(0xffffffffu, mj1, 1));
        mj1 = fmaxf(mj1, __shfl_xor_sync(0xffffffffu, mj1, 2));
        const float mn0 = fmaxf(m0, mj0);
        const float mn1 = fmaxf(m1, mj1);
        const float a0 = exp2f(m0 - mn0);
        const float a1 = exp2f(m1 - mn1);
        m0 = mn0; m1 = mn1;

        float sum0 = 0.0f, sum1 = 0.0f;
        uint32_t pa[8][4];
#pragma unroll
        for (int t = 0; t < 8; t++) {
            const float e00 = exp2f(s[2 * t][0] - m0),     e01 = exp2f(s[2 * t][1] - m0);
            const float e02 = exp2f(s[2 * t][2] - m1),     e03 = exp2f(s[2 * t][3] - m1);
            const float e10 = exp2f(s[2 * t + 1][0] - m0), e11 = exp2f(s[2 * t + 1][1] - m0);
            const float e12 = exp2f(s[2 * t + 1][2] - m1), e13 = exp2f(s[2 * t + 1][3] - m1);
            sum0 += (e00 + e01) + (e10 + e11);
            sum1 += (e02 + e03) + (e12 + e13);
            pa[t][0] = h2pack(e00, e01);
            pa[t][1] = h2pack(e02, e03);
            pa[t][2] = h2pack(e10, e11);
            pa[t][3] = h2pack(e12, e13);
        }
        // full row sum: reduce across the 4 threads of each quad
        sum0 += __shfl_xor_sync(0xffffffffu, sum0, 1);
        sum0 += __shfl_xor_sync(0xffffffffu, sum0, 2);
        sum1 += __shfl_xor_sync(0xffffffffu, sum1, 1);
        sum1 += __shfl_xor_sync(0xffffffffu, sum1, 2);
        l0 = l0 * a0 + sum0;
        l1 = l1 * a1 + sum1;
#pragma unroll
        for (int i = 0; i < 16; i++) {
            o[i][0] *= a0; o[i][1] *= a0;
            o[i][2] *= a1; o[i][3] *= a1;
        }

        // ---- O += P·V  (B = Vt tile: [hd][kv]) ----
#pragma unroll
        for (int t = 0; t < 8; t++) {
            const int cbv = t * 2 + (lane >> 4);
            uint32_t vf[4];
#pragma unroll
            for (int u = 0; u < 8; u++) {
                ldm4(vf, kb + FL_TILE_B + fl_phys(u * 16 + nrow, cbv));
                mma16816h(o[2 * u],     pa[t], vf[0], vf[2]);
                mma16816h(o[2 * u + 1], pa[t], vf[1], vf[3]);
            }
        }
    }

    // ---- epilogue: normalize and store fp16 ----
    const int g  = lane >> 2;
    const int tg = lane & 3;
    const float r0 = 1.0f / l0;
    const float r1 = 1.0f / l1;
    const size_t row0 = (size_t)(q0 + wid * 16 + g) * D_MODEL + h * HD;
    const size_t row1 = row0 + (size_t)8 * D_MODEL;
#pragma unroll
    for (int nb = 0; nb < 16; nb++) {
        const int col = nb * 8 + tg * 2;
        *(uint32_t*)(at16 + row0 + col) = h2pack(o[nb][0] * r0, o[nb][1] * r0);
        *(uint32_t*)(at16 + row1 + col) = h2pack(o[nb][2] * r1, o[nb][3] * r1);
    }
}

// =============================================================================
// convert kernel: fp32 -> fp16
// =============================================================================
__global__ void __launch_bounds__(256) cvt16_kernel(
    const float* __restrict__ src, __half* __restrict__ dst, long long n4)
{
    const long long i = (long long)blockIdx.x * 256 + threadIdx.x;
    if (i >= n4) return;
    float4 v = ((const float4*)src)[i];
    uint2 o;
    o.x = h2pack(v.x, v.y);
    o.y = h2pack(v.z, v.w);
    ((uint2*)dst)[i] = o;
}

// =============================================================================
// RoPE + convert: q gets pre-scaled by SCALE_LOG2E for exp2-space softmax
// =============================================================================
__global__ void __launch_bounds__(1024) rope_kernel(
    const float* __restrict__ qkv,
    __half* __restrict__ q16, __half* __restrict__ k16)
{
    __shared__ float s_inv[64];
    const int s = blockIdx.x;
    const int t = threadIdx.x;
    if (t < 64) s_inv[t] = (float)pow(10000.0, -(double)(2 * t) / 128.0);
    __syncthreads();

    const int h = t >> 6;
    const int j = t & 63;
    const float ang = (float)((double)s * (double)s_inv[j]);
    float sn, cs;
    sincosf(ang, &sn, &cs);

    const float* q = qkv + (size_t)s * E3 + h * HD;
    const float* k = q + D_MODEL;
    const size_t ob = (size_t)s * D_MODEL + h * HD;

    const float q1 = q[j], q2 = q[j + 64];
    const float k1 = k[j], k2 = k[j + 64];
    q16[ob + j]      = __float2half_rn((q1 * cs - q2 * sn) * SCALE_LOG2E);
    q16[ob + j + 64] = __float2half_rn((q2 * cs + q1 * sn) * SCALE_LOG2E);
    k16[ob + j]      = __float2half_rn(k1 * cs - k2 * sn);
    k16[ob + j + 64] = __float2half_rn(k2 * cs + k1 * sn);
}

// =============================================================================
// V transpose + convert: vt[c][s] = qkv[s][2D + c]
// =============================================================================
__global__ void __launch_bounds__(256) vtrans_kernel(
    const float* __restrict__ qkv, __half* __restrict__ vt16)
{
    __shared__ float tile[32][33];
    const int c0 = blockIdx.x * 32;
    const int s0 = blockIdx.y * 32;
    const int tx = threadIdx.x & 31;
    const int ty = threadIdx.x >> 5;

#pragma unroll
    for (int r = ty; r < 32; r += 8)
        tile[r][tx] = qkv[(size_t)(s0 + r) * E3 + 2 * D_MODEL + c0 + tx];
    __syncthreads();
#pragma unroll
    for (int r = ty; r < 32; r += 8)
        vt16[(size_t)(c0 + r) * S_LEN + s0 + tx] = __float2half_rn(tile[tx][r]);
}

// =============================================================================
// launch
// =============================================================================
extern "C" void kernel_launch(void* const* d_in, const int* in_sizes, int n_in,
                              void* d_out, int out_size)
{
    (void)in_sizes; (void)n_in; (void)out_size;
    const float* x     = (const float*)d_in[0];   // [1, 2048, 2048]
    const float* w_qkv = (const float*)d_in[1];   // [6144, 2048]
    const float* w_out = (const float*)d_in[2];   // [2048, 2048]
    float* out = (float*)d_out;                   // [1, 2048, 2048]

    float* qkv;
    cudaGetSymbolAddress((void**)&qkv, g_qkv);
    __half *x16, *wq16, *wo16, *q16, *k16, *vt16, *at16;
    cudaGetSymbolAddress((void**)&x16,  g_x16);
    cudaGetSymbolAddress((void**)&wq16, g_wq16);
    cudaGetSymbolAddress((void**)&wo16, g_wo16);
    cudaGetSymbolAddress((void**)&q16,  g_q16);
    cudaGetSymbolAddress((void**)&k16,  g_k16);
    cudaGetSymbolAddress((void**)&vt16, g_vt16);
    cudaGetSymbolAddress((void**)&at16, g_at16);

    cudaFuncSetAttribute(gemm_tc_kernel, cudaFuncAttributeMaxDynamicSharedMemorySize, GEMM_SMEM);
    cudaFuncSetAttribute(flash_kernel,   cudaFuncAttributeMaxDynamicSharedMemorySize, FLASH_SMEM);

    // 0) convert inputs to fp16
    {
        long long n4;
        n4 = (long long)S_LEN * D_MODEL / 4;
        cvt16_kernel<<<(unsigned)((n4 + 255) / 256), 256>>>(x, x16, n4);
        n4 = (long long)E3 * D_MODEL / 4;
        cvt16_kernel<<<(unsigned)((n4 + 255) / 256), 256>>>(w_qkv, wq16, n4);
        n4 = (long long)D_MODEL * D_MODEL / 4;
        cvt16_kernel<<<(unsigned)((n4 + 255) / 256), 256>>>(w_out, wo16, n4);
    }

    // 1) QKV projection (fp32 out)
    {
        dim3 grid(E3 / 256, S_LEN / 128, 1);
        gemm_tc_kernel<<<grid, 256, GEMM_SMEM>>>(x16, wq16, qkv,
                                                 D_MODEL, D_MODEL, D_MODEL, E3, 1.0f);
    }

    // 2) RoPE -> q16 (pre-scaled), k16 ; transpose v -> vt16
    rope_kernel<<<S_LEN, 1024>>>(qkv, q16, k16);
    {
        dim3 grid(D_MODEL / 32, S_LEN / 32, 1);
        vtrans_kernel<<<grid, 256>>>(qkv, vt16);
    }

    // 3) flash attention: scores + softmax + PV fused -> at16
    {
        dim3 grid(S_LEN / 128, N_HEADS, 1);
        flash_kernel<<<grid, 256, FLASH_SMEM>>>(q16, k16, vt16, at16);
    }

    // 4) out projection (fp32 out)
    {
        dim3 grid(D_MODEL / 256, S_LEN / 128, 1);
        gemm_tc_kernel<<<grid, 256, GEMM_SMEM>>>(at16, wo16, out,
                                                 D_MODEL, D_MODEL, D_MODEL, D_MODEL, 1.0f);
    }
}

// round 13
// speedup vs baseline: 2.9795x; 1.0325x over previous
#include <cuda_runtime.h>
#include <cuda_fp16.h>
#include <math.h>
#include <stdint.h>

#define S_LEN 2048
#define D_MODEL 2048
#define N_HEADS 16
#define HD 128
#define E3 (3 * D_MODEL)   // 6144

// softmax scale folded with log2(e): softmax(s*scale) == exp2-softmax(s*scale*log2e)
#define SCALE_LOG2E (0.08838834764831845f * 1.4426950408889634f)

// ---------------- scratch (static device globals; no allocations) -------------
__device__ __half g_x16[(size_t)S_LEN * D_MODEL];
__device__ __half g_wq16[(size_t)E3 * D_MODEL];
__device__ __half g_wo16[(size_t)D_MODEL * D_MODEL];
__device__ __half g_q16[(size_t)S_LEN * D_MODEL];    // rope'd, pre-scaled by SCALE_LOG2E
__device__ __half g_k16[(size_t)S_LEN * D_MODEL];    // rope'd
__device__ __half g_vt16[(size_t)D_MODEL * S_LEN];   // V transposed: [hd_global][s]
__device__ __half g_at16[(size_t)S_LEN * D_MODEL];   // attention output fp16

// =============================================================================
// helpers (base-ISA only: mma.sync / ldmatrix / cp.async)
// =============================================================================
__device__ __forceinline__ uint32_t smem_u32(const void* p) {
    uint32_t a;
    asm("{ .reg .u64 t; cvta.to.shared.u64 t, %1; cvt.u32.u64 %0, t; }" : "=r"(a) : "l"(p));
    return a;
}
__device__ __forceinline__ void cp16(uint32_t dst, const void* src) {
    asm volatile("cp.async.cg.shared.global [%0], [%1], 16;" :: "r"(dst), "l"(src));
}
#define CP_COMMIT() asm volatile("cp.async.commit_group;" ::: "memory")
#define CP_WAIT(n)  asm volatile("cp.async.wait_group %0;" :: "n"(n) : "memory")

__device__ __forceinline__ void ldm4(uint32_t* r, uint32_t addr) {
    asm volatile("ldmatrix.sync.aligned.m8n8.x4.shared.b16 {%0,%1,%2,%3}, [%4];"
                 : "=r"(r[0]), "=r"(r[1]), "=r"(r[2]), "=r"(r[3]) : "r"(addr));
}
__device__ __forceinline__ void mma16816h(float* d, const uint32_t* a, uint32_t b0, uint32_t b1) {
    asm volatile(
        "mma.sync.aligned.m16n8k16.row.col.f32.f16.f16.f32 "
        "{%0,%1,%2,%3}, {%4,%5,%6,%7}, {%8,%9}, {%0,%1,%2,%3};"
        : "+f"(d[0]), "+f"(d[1]), "+f"(d[2]), "+f"(d[3])
        : "r"(a[0]), "r"(a[1]), "r"(a[2]), "r"(a[3]), "r"(b0), "r"(b1));
}
__device__ __forceinline__ uint32_t h2pack(float a, float b) {
    __half2 h = __floats2half2_rn(a, b);
    return *(uint32_t*)&h;
}

// =============================================================================
// shared GEMM mainloop config: CTA tile 128x256, K-tile 64, 4-stage cp.async,
// 256 threads, 8 warps as 2(m) x 4(n), warp tile 64x64.
// =============================================================================
#define TILE_A_B 16384               // A: 128 rows * 128B
#define TILE_B_B 32768               // B: 256 rows * 128B
#define STAGE_B (TILE_A_B + TILE_B_B)
#define NSTAGE 4
#define GEMM_SMEM (NSTAGE * STAGE_B) // 192 KB

// mainloop as a macro-like inline: computes acc[4][8][4] for (m0, n0)
#define GEMM_MAINLOOP(A_, B_, K_, lda_, ldb_)                                   \
    const int nt = (K_) / 64;                                                   \
    auto load_stage = [&](int t, int bufi) {                                    \
        const uint32_t base = sb + (uint32_t)bufi * STAGE_B;                    \
        _Pragma("unroll")                                                       \
        for (int i = 0; i < 4; i++) {                                           \
            const int cid = tid + 256 * i;                                      \
            const int row = cid >> 3;                                           \
            const int c   = cid & 7;                                            \
            const uint32_t phys = (uint32_t)(row * 128 + ((c ^ (row & 7)) << 4));\
            cp16(base + phys, (A_) + (size_t)(m0 + row) * (lda_) + (size_t)t * 64 + c * 8); \
        }                                                                       \
        _Pragma("unroll")                                                       \
        for (int i = 0; i < 8; i++) {                                           \
            const int cid = tid + 256 * i;                                      \
            const int row = cid >> 3;                                           \
            const int c   = cid & 7;                                            \
            const uint32_t phys = (uint32_t)(row * 128 + ((c ^ (row & 7)) << 4));\
            cp16(base + TILE_A_B + phys, (B_) + (size_t)(n0 + row) * (ldb_) + (size_t)t * 64 + c * 8); \
        }                                                                       \
        CP_COMMIT();                                                            \
    };                                                                          \
    load_stage(0, 0);                                                           \
    if (nt > 1) load_stage(1, 1);                                               \
    if (nt > 2) load_stage(2, 2);                                               \
    const int ar = wm * 64 + (lane & 15);                                       \
    const int br = wn * 64 + (lane & 15);                                       \
    int buf = 0;                                                                \
    for (int t = 0; t < nt; t++) {                                              \
        if (t + 1 < nt) {                                                       \
            if (t + 2 < nt) { CP_WAIT(2); } else { CP_WAIT(1); }                \
        } else {                                                                \
            CP_WAIT(0);                                                         \
        }                                                                       \
        __syncthreads();                                                        \
        if (t + 3 < nt) {                                                       \
            int nb_ = buf + 3; if (nb_ >= NSTAGE) nb_ -= NSTAGE;                \
            load_stage(t + 3, nb_);                                             \
        }                                                                       \
        const uint32_t tb = sb + (uint32_t)buf * STAGE_B;                       \
        _Pragma("unroll")                                                       \
        for (int k16 = 0; k16 < 4; k16++) {                                     \
            const int cb = k16 * 2 + (lane >> 4);                               \
            uint32_t af[4][4];                                                  \
            _Pragma("unroll")                                                   \
            for (int mb = 0; mb < 4; mb++) {                                    \
                const int R = ar + mb * 16;                                     \
                ldm4(af[mb], tb + (uint32_t)(R * 128 + ((cb ^ (R & 7)) << 4))); \
            }                                                                   \
            uint32_t bfr[4][4];                                                 \
            _Pragma("unroll")                                                   \
            for (int q = 0; q < 4; q++) {                                       \
                const int R = br + q * 16;                                      \
                ldm4(bfr[q], tb + TILE_A_B + (uint32_t)(R * 128 + ((cb ^ (R & 7)) << 4))); \
            }                                                                   \
            _Pragma("unroll")                                                   \
            for (int mb = 0; mb < 4; mb++)                                      \
                _Pragma("unroll")                                               \
                for (int q = 0; q < 4; q++) {                                   \
                    mma16816h(acc[mb][2 * q],     af[mb], bfr[q][0], bfr[q][2]);\
                    mma16816h(acc[mb][2 * q + 1], af[mb], bfr[q][1], bfr[q][3]);\
                }                                                               \
        }                                                                       \
        if (++buf == NSTAGE) buf = 0;                                           \
    }

// =============================================================================
// out-projection GEMM: fp32 C output
// =============================================================================
__global__ void __launch_bounds__(256, 1) gemm_tc_kernel(
    const __half* __restrict__ A, const __half* __restrict__ B,
    float* __restrict__ C,
    int K, int lda, int ldb, int ldc, float scale)
{
    extern __shared__ __align__(128) char smem[];
    const uint32_t sb = smem_u32(smem);
    const int tid = threadIdx.x;
    const int lane = tid & 31;
    const int wid = tid >> 5;
    const int wm = wid & 1;
    const int wn = wid >> 1;
    const int m0 = blockIdx.y * 128;
    const int n0 = blockIdx.x * 256;

    float acc[4][8][4];
#pragma unroll
    for (int a = 0; a < 4; a++)
#pragma unroll
        for (int b = 0; b < 8; b++)
#pragma unroll
            for (int c = 0; c < 4; c++) acc[a][b][c] = 0.0f;

    GEMM_MAINLOOP(A, B, K, lda, ldb)

    const int g  = lane >> 2;
    const int tg = lane & 3;
#pragma unroll
    for (int mb = 0; mb < 4; mb++) {
        const int row = m0 + wm * 64 + mb * 16 + g;
#pragma unroll
        for (int nb = 0; nb < 8; nb++) {
            const int col = n0 + wn * 64 + nb * 8 + tg * 2;
            float2 v0, v1;
            v0.x = acc[mb][nb][0] * scale; v0.y = acc[mb][nb][1] * scale;
            v1.x = acc[mb][nb][2] * scale; v1.y = acc[mb][nb][3] * scale;
            *(float2*)(C + (size_t)row * ldc + col)       = v0;
            *(float2*)(C + (size_t)(row + 8) * ldc + col) = v1;
        }
    }
}

// =============================================================================
// fused QKV GEMM: mainloop as above, epilogue stages the fp32 tile to smem and
// then applies RoPE (q/k regions) or transpose (v region), writing fp16 directly.
// Region by n0: [0,2048)=q, [2048,4096)=k, [4096,6144)=v.
// =============================================================================
#define FT_LD 261   // padded fp32 tile row stride (5 coprime 32 -> conflict-free cols)

__global__ void __launch_bounds__(256, 1) gemm_qkv_kernel(
    const __half* __restrict__ A, const __half* __restrict__ B,
    __half* __restrict__ q16, __half* __restrict__ k16, __half* __restrict__ vt16)
{
    extern __shared__ __align__(128) char smem[];
    const uint32_t sb = smem_u32(smem);
    const int tid = threadIdx.x;
    const int lane = tid & 31;
    const int wid = tid >> 5;
    const int wm = wid & 1;
    const int wn = wid >> 1;
    const int m0 = blockIdx.y * 128;
    const int n0 = blockIdx.x * 256;

    float acc[4][8][4];
#pragma unroll
    for (int a = 0; a < 4; a++)
#pragma unroll
        for (int b = 0; b < 8; b++)
#pragma unroll
            for (int c = 0; c < 4; c++) acc[a][b][c] = 0.0f;

    GEMM_MAINLOOP(A, B, D_MODEL, D_MODEL, D_MODEL)

    // ---- stage fp32 tile to smem ----
    __syncthreads();   // all MMA smem reads done; safe to repurpose buffers
    float* ftile = (float*)smem;                 // [128][FT_LD]
    float* s_inv = ftile + 128 * FT_LD;          // 64 floats
    if (tid < 64) s_inv[tid] = (float)pow(10000.0, -(double)(2 * tid) / 128.0);

    const int g  = lane >> 2;
    const int tg = lane & 3;
#pragma unroll
    for (int mb = 0; mb < 4; mb++) {
        const int row = wm * 64 + mb * 16 + g;
#pragma unroll
        for (int nb = 0; nb < 8; nb++) {
            const int col = wn * 64 + nb * 8 + tg * 2;
            ftile[row * FT_LD + col]           = acc[mb][nb][0];
            ftile[row * FT_LD + col + 1]       = acc[mb][nb][1];
            ftile[(row + 8) * FT_LD + col]     = acc[mb][nb][2];
            ftile[(row + 8) * FT_LD + col + 1] = acc[mb][nb][3];
        }
    }
    __syncthreads();

    const int region = n0 >> 11;   // 0=q, 1=k, 2=v
    if (region < 2) {
        __half* dst = (region == 0) ? q16 : k16;
        const float qs = (region == 0) ? SCALE_LOG2E : 1.0f;
        const int pc = tid & 127;          // pair-column 0..127
        const int hl = pc >> 6;            // head-local 0/1
        const int j  = pc & 63;
        const int rb = (tid >> 7) * 64;    // row base 0 or 64
        const int e_base = (n0 & 2047) + hl * 128;
        const float invf = s_inv[j];
        for (int r = 0; r < 64; r++) {
            const int row = rb + r;
            const int s   = m0 + row;
            const float v1 = ftile[row * FT_LD + hl * 128 + j];
            const float v2 = ftile[row * FT_LD + hl * 128 + j + 64];
            const float ang = (float)((double)s * (double)invf);
            float sn, cs;
            sincosf(ang, &sn, &cs);
            dst[(size_t)s * D_MODEL + e_base + j]      = __float2half_rn((v1 * cs - v2 * sn) * qs);
            dst[(size_t)s * D_MODEL + e_base + j + 64] = __float2half_rn((v2 * cs + v1 * sn) * qs);
        }
    } else {
        // v region: transpose -> vt16[channel][s]
        const int e = tid;                 // local channel 0..255
        __half* vr = vt16 + (size_t)(n0 - 4096 + e) * S_LEN + m0;
#pragma unroll
        for (int k = 0; k < 16; k++) {
            __align__(16) __half tmp[8];
#pragma unroll
            for (int i = 0; i < 8; i++)
                tmp[i] = __float2half_rn(ftile[(8 * k + i) * FT_LD + e]);
            *(uint4*)(vr + 8 * k) = *(uint4*)tmp;
        }
    }
}

// =============================================================================
// flash attention: one CTA = (head, 128-row q tile). (unchanged from R12 champion)
// =============================================================================
#define FL_TILE_B 32768              // 128 * 256B
#define FL_Q_OFF 0
#define FL_S_OFF 32768
#define FL_STAGE_B (2 * FL_TILE_B)   // K tile + Vt tile
#define FL_NKV 16                    // 2048 / 128
#define FLASH_SMEM (FL_S_OFF + 3 * FL_STAGE_B)   // 32KB + 192KB = 224KB

__device__ __forceinline__ uint32_t fl_phys(int row, int c) {
    return (uint32_t)(row * 256 + ((c ^ ((row & 7) << 1)) << 4));
}

__global__ void __launch_bounds__(256, 1) flash_kernel(
    const __half* __restrict__ q16, const __half* __restrict__ k16,
    const __half* __restrict__ vt16, __half* __restrict__ at16)
{
    extern __shared__ __align__(128) char smem[];
    const uint32_t sb = smem_u32(smem);
    const int tid = threadIdx.x;
    const int lane = tid & 31;
    const int wid = tid >> 5;
    const int h = blockIdx.y;
    const int q0 = blockIdx.x * 128;

#pragma unroll
    for (int i = 0; i < 8; i++) {
        const int cid = tid + 256 * i;
        const int row = cid >> 4;
        const int c   = cid & 15;
        cp16(sb + FL_Q_OFF + fl_phys(row, c),
             q16 + (size_t)(q0 + row) * D_MODEL + h * HD + c * 8);
    }
    auto load_kv = [&](int j, int buf) {
        const uint32_t base = sb + FL_S_OFF + (uint32_t)buf * FL_STAGE_B;
#pragma unroll
        for (int i = 0; i < 8; i++) {
            const int cid = tid + 256 * i;
            const int row = cid >> 4;
            const int c   = cid & 15;
            cp16(base + fl_phys(row, c),
                 k16 + (size_t)(j * 128 + row) * D_MODEL + h * HD + c * 8);
            cp16(base + FL_TILE_B + fl_phys(row, c),
                 vt16 + (size_t)(h * HD + row) * S_LEN + j * 128 + c * 8);
        }
        CP_COMMIT();
    };
    load_kv(0, 0);
    load_kv(1, 1);

    float o[16][4];
#pragma unroll
    for (int i = 0; i < 16; i++)
#pragma unroll
        for (int c = 0; c < 4; c++) o[i][c] = 0.0f;
    float m0 = -INFINITY, m1 = -INFINITY, l0 = 0.0f, l1 = 0.0f;

    const int arow = wid * 16 + (lane & 15);
    const int nrow = lane & 15;

    CP_WAIT(1);
    __syncthreads();
    uint32_t qf[8][4];
#pragma unroll
    for (int kk = 0; kk < 8; kk++) {
        const int cb = kk * 2 + (lane >> 4);
        ldm4(qf[kk], sb + FL_Q_OFF + fl_phys(arow, cb));
    }

    for (int j = 0; j < FL_NKV; j++) {
        if (j + 1 < FL_NKV) { CP_WAIT(1); } else { CP_WAIT(0); }
        __syncthreads();
        if (j + 2 < FL_NKV) {
            int nb = j + 2; load_kv(nb, nb % 3);
        }
        const uint32_t kb = sb + FL_S_OFF + (uint32_t)(j % 3) * FL_STAGE_B;

        float s[16][4];
#pragma unroll
        for (int i = 0; i < 16; i++)
#pragma unroll
            for (int c = 0; c < 4; c++) s[i][c] = 0.0f;

#pragma unroll
        for (int kk = 0; kk < 8; kk++) {
            const int cb = kk * 2 + (lane >> 4);
            uint32_t bf[4];
#pragma unroll
            for (int t = 0; t < 8; t++) {
                ldm4(bf, kb + fl_phys(t * 16 + nrow, cb));
                mma16816h(s[2 * t],     qf[kk], bf[0], bf[2]);
                mma16816h(s[2 * t + 1], qf[kk], bf[1], bf[3]);
            }
        }

        float mj0 = -INFINITY, mj1 = -INFINITY;
#pragma unroll
        for (int i = 0; i < 16; i++) {
            mj0 = fmaxf(mj0, fmaxf(s[i][0], s[i][1]));
            mj1 = fmaxf(mj1, fmaxf(s[i][2], s[i][3]));
        }
        mj0 = fmaxf(mj0, __shfl_xor_sync(0xffffffffu, mj0, 1));
        mj0 = fmaxf(mj0, __shfl_xor_sync(0xffffffffu, mj0, 2));
        mj1 = fmaxf(mj1, __shfl_xor_sync(0xffffffffu, mj1, 1));
        mj1 = fmaxf(mj1, __shfl_xor_sync(0xffffffffu, mj1, 2));
        const float mn0 = fmaxf(m0, mj0);
        const float mn1 = fmaxf(m1, mj1);
        const float a0 = exp2f(m0 - mn0);
        const float a1 = exp2f(m1 - mn1);
        m0 = mn0; m1 = mn1;

        float sum0 = 0.0f, sum1 = 0.0f;
        uint32_t pa[8][4];
#pragma unroll
        for (int t = 0; t < 8; t++) {
            const float e00 = exp2f(s[2 * t][0] - m0),     e01 = exp2f(s[2 * t][1] - m0);
            const float e02 = exp2f(s[2 * t][2] - m1),     e03 = exp2f(s[2 * t][3] - m1);
            const float e10 = exp2f(s[2 * t + 1][0] - m0), e11 = exp2f(s[2 * t + 1][1] - m0);
            const float e12 = exp2f(s[2 * t + 1][2] - m1), e13 = exp2f(s[2 * t + 1][3] - m1);
            sum0 += (e00 + e01) + (e10 + e11);
            sum1 += (e02 + e03) + (e12 + e13);
            pa[t][0] = h2pack(e00, e01);
            pa[t][1] = h2pack(e02, e03);
            pa[t][2] = h2pack(e10, e11);
            pa[t][3] = h2pack(e12, e13);
        }
        sum0 += __shfl_xor_sync(0xffffffffu, sum0, 1);
        sum0 += __shfl_xor_sync(0xffffffffu, sum0, 2);
        sum1 += __shfl_xor_sync(0xffffffffu, sum1, 1);
        sum1 += __shfl_xor_sync(0xffffffffu, sum1, 2);
        l0 = l0 * a0 + sum0;
        l1 = l1 * a1 + sum1;
#pragma unroll
        for (int i = 0; i < 16; i++) {
            o[i][0] *= a0; o[i][1] *= a0;
            o[i][2] *= a1; o[i][3] *= a1;
        }

#pragma unroll
        for (int t = 0; t < 8; t++) {
            const int cbv = t * 2 + (lane >> 4);
            uint32_t vf[4];
#pragma unroll
            for (int u = 0; u < 8; u++) {
                ldm4(vf, kb + FL_TILE_B + fl_phys(u * 16 + nrow, cbv));
                mma16816h(o[2 * u],     pa[t], vf[0], vf[2]);
                mma16816h(o[2 * u + 1], pa[t], vf[1], vf[3]);
            }
        }
    }

    const int g  = lane >> 2;
    const int tg = lane & 3;
    const float r0 = 1.0f / l0;
    const float r1 = 1.0f / l1;
    const size_t row0 = (size_t)(q0 + wid * 16 + g) * D_MODEL + h * HD;
    const size_t row1 = row0 + (size_t)8 * D_MODEL;
#pragma unroll
    for (int nb = 0; nb < 16; nb++) {
        const int col = nb * 8 + tg * 2;
        *(uint32_t*)(at16 + row0 + col) = h2pack(o[nb][0] * r0, o[nb][1] * r0);
        *(uint32_t*)(at16 + row1 + col) = h2pack(o[nb][2] * r1, o[nb][3] * r1);
    }
}

// =============================================================================
// convert kernel: fp32 -> fp16
// =============================================================================
__global__ void __launch_bounds__(256) cvt16_kernel(
    const float* __restrict__ src, __half* __restrict__ dst, long long n4)
{
    const long long i = (long long)blockIdx.x * 256 + threadIdx.x;
    if (i >= n4) return;
    float4 v = ((const float4*)src)[i];
    uint2 o;
    o.x = h2pack(v.x, v.y);
    o.y = h2pack(v.z, v.w);
    ((uint2*)dst)[i] = o;
}

// =============================================================================
// launch
// =============================================================================
extern "C" void kernel_launch(void* const* d_in, const int* in_sizes, int n_in,
                              void* d_out, int out_size)
{
    (void)in_sizes; (void)n_in; (void)out_size;
    const float* x     = (const float*)d_in[0];   // [1, 2048, 2048]
    const float* w_qkv = (const float*)d_in[1];   // [6144, 2048]
    const float* w_out = (const float*)d_in[2];   // [2048, 2048]
    float* out = (float*)d_out;                   // [1, 2048, 2048]

    __half *x16, *wq16, *wo16, *q16, *k16, *vt16, *at16;
    cudaGetSymbolAddress((void**)&x16,  g_x16);
    cudaGetSymbolAddress((void**)&wq16, g_wq16);
    cudaGetSymbolAddress((void**)&wo16, g_wo16);
    cudaGetSymbolAddress((void**)&q16,  g_q16);
    cudaGetSymbolAddress((void**)&k16,  g_k16);
    cudaGetSymbolAddress((void**)&vt16, g_vt16);
    cudaGetSymbolAddress((void**)&at16, g_at16);

    cudaFuncSetAttribute(gemm_tc_kernel,  cudaFuncAttributeMaxDynamicSharedMemorySize, GEMM_SMEM);
    cudaFuncSetAttribute(gemm_qkv_kernel, cudaFuncAttributeMaxDynamicSharedMemorySize, GEMM_SMEM);
    cudaFuncSetAttribute(flash_kernel,    cudaFuncAttributeMaxDynamicSharedMemorySize, FLASH_SMEM);

    // 0) convert inputs to fp16
    {
        long long n4;
        n4 = (long long)S_LEN * D_MODEL / 4;
        cvt16_kernel<<<(unsigned)((n4 + 255) / 256), 256>>>(x, x16, n4);
        n4 = (long long)E3 * D_MODEL / 4;
        cvt16_kernel<<<(unsigned)((n4 + 255) / 256), 256>>>(w_qkv, wq16, n4);
        n4 = (long long)D_MODEL * D_MODEL / 4;
        cvt16_kernel<<<(unsigned)((n4 + 255) / 256), 256>>>(w_out, wo16, n4);
    }

    // 1) fused QKV projection + RoPE + V transpose -> q16, k16, vt16
    {
        dim3 grid(E3 / 256, S_LEN / 128, 1);
        gemm_qkv_kernel<<<grid, 256, GEMM_SMEM>>>(x16, wq16, q16, k16, vt16);
    }

    // 2) flash attention: scores + softmax + PV fused -> at16
    {
        dim3 grid(S_LEN / 128, N_HEADS, 1);
        flash_kernel<<<grid, 256, FLASH_SMEM>>>(q16, k16, vt16, at16);
    }

    // 3) out projection (fp32 out)
    {
        dim3 grid(D_MODEL / 256, S_LEN / 128, 1);
        gemm_tc_kernel<<<grid, 256, GEMM_SMEM>>>(at16, wo16, out,
                                                 D_MODEL, D_MODEL, D_MODEL, D_MODEL, 1.0f);
    }
}